// round 5
// baseline (speedup 1.0000x reference)
#include <cuda_runtime.h>
#include <cstdint>

#define NN 200000
#define NPAD 200064     // 1563 * 128
#define DD 128
#define EE 200000
#define EE2 20000
#define SS 6
#define LL 4
#define NBLK 1563
#define ARB 136         // B smem stride (floats): conflict-free b-frags
#define ARA 132         // A smem stride (floats): conflict-free a-frags row-major
#define NTYPE 14
#define CAP3 16         // edges per (type,u) bucket

// ---------------- device scratch ----------------
__device__ float g_feat[NPAD * DD];
__device__ float g_y   [NPAD * DD];
__device__ float g_tmp [NPAD * DD];
__device__ int   g_cnt3[NTYPE * NPAD];
__device__ int   g_edg3[NTYPE * NPAD * CAP3];   // 44.8M ints

__device__ __forceinline__ float4 ld4(const float* p) { return *(const float4*)(p); }

__device__ __forceinline__ float tf32r(float x) {
    float y;
    asm("cvt.rna.tf32.f32 %0, %1;" : "=f"(y) : "f"(x));
    return y;
}

__device__ __forceinline__ float wsum(float s) {
#pragma unroll
    for (int o = 16; o; o >>= 1) s += __shfl_xor_sync(0xffffffffu, s, o);
    return s;
}

#define MMA_TF32(acc, a0, a1, a2, a3, b0, b1) \
    asm volatile( \
        "mma.sync.aligned.m16n8k8.row.col.f32.tf32.tf32.f32 " \
        "{%0,%1,%2,%3}, {%4,%5,%6,%7}, {%8,%9}, {%0,%1,%2,%3};\n" \
        : "+f"((acc)[0]), "+f"((acc)[1]), "+f"((acc)[2]), "+f"((acc)[3]) \
        : "r"(a0), "r"(a1), "r"(a2), "r"(a3), "r"(b0), "r"(b1))

// ---------------- edge bucket build: per (type, u) lists ----------------
__global__ void place_kernel(const int* __restrict__ pre_u, const int* __restrict__ pre_v,
                             const int* __restrict__ suc_u, const int* __restrict__ suc_v,
                             const int* __restrict__ left_u, const int* __restrict__ left_v,
                             const int* __restrict__ right_u, const int* __restrict__ right_v)
{
    int idx = blockIdx.x * 256 + threadIdx.x;
    int t, u, v;
    const int TOT = 12 * EE + 2 * EE2;
    if (idx < 6 * EE)            { t = idx / EE; u = pre_u[idx]; v = pre_v[idx]; }
    else if (idx < 12 * EE)      { int j = idx - 6 * EE; t = idx / EE; u = suc_u[j]; v = suc_v[j]; }
    else if (idx < 12 * EE + EE2){ int j = idx - 12 * EE; t = 12; u = left_u[j]; v = left_v[j]; }
    else if (idx < TOT)          { int j = idx - 12 * EE - EE2; t = 13; u = right_u[j]; v = right_v[j]; }
    else return;
    int b = t * NPAD + u;
    int pos = atomicAdd(&g_cnt3[b], 1);
    if (pos < CAP3) g_edg3[b * CAP3 + pos] = v;
}

// ---------------- encoder stage 1 ----------------
__global__ __launch_bounds__(256) void enc1_kernel(
    const float* __restrict__ ctrs, const float* __restrict__ feats,
    const float* __restrict__ w_in1, const float* __restrict__ b_in1,
    const float* __restrict__ w_seg1, const float* __restrict__ b_seg1,
    float* __restrict__ h_in, float* __restrict__ h_seg)
{
    int idx = blockIdx.x * blockDim.x + threadIdx.x;
    int n = idx >> 5;
    if (n >= NN) return;
    int c = (idx & 31) * 4;

    float c0 = __ldg(&ctrs[2 * n]),  c1 = __ldg(&ctrs[2 * n + 1]);
    float f0 = __ldg(&feats[2 * n]), f1 = __ldg(&feats[2 * n + 1]);

    float4 wi0 = ld4(w_in1 + c), wi1 = ld4(w_in1 + DD + c), bi = ld4(b_in1 + c);
    float4 ws0 = ld4(w_seg1 + c), ws1 = ld4(w_seg1 + DD + c), bs = ld4(b_seg1 + c);

    float4 hi, hs;
    hi.x = fmaxf(c0 * wi0.x + c1 * wi1.x + bi.x, 0.f);
    hi.y = fmaxf(c0 * wi0.y + c1 * wi1.y + bi.y, 0.f);
    hi.z = fmaxf(c0 * wi0.z + c1 * wi1.z + bi.z, 0.f);
    hi.w = fmaxf(c0 * wi0.w + c1 * wi1.w + bi.w, 0.f);
    hs.x = fmaxf(f0 * ws0.x + f1 * ws1.x + bs.x, 0.f);
    hs.y = fmaxf(f0 * ws0.y + f1 * ws1.y + bs.y, 0.f);
    hs.z = fmaxf(f0 * ws0.z + f1 * ws1.z + bs.z, 0.f);
    hs.w = fmaxf(f0 * ws0.w + f1 * ws1.w + bs.w, 0.f);

    *(float4*)&h_in [n * DD + c] = hi;
    *(float4*)&h_seg[n * DD + c] = hs;
}

// ---------------- encoder GEMM pair (in-place, row-local) ----------------
__global__ __launch_bounds__(256, 2) void enc_gemm2_kernel(
    float* __restrict__ Ain, const float* __restrict__ Ba,
    float* __restrict__ Aseg, const float* __restrict__ Bb)
{
    extern __shared__ float sm[];
    float* Bs = sm;               // [128][ARB]
    float* As = sm + 128 * ARB;   // [32][ARB]

    int tid = threadIdx.x, lane = tid & 31, warp = tid >> 5;
    int gid = lane >> 2, tig = lane & 3;
    int wm = warp >> 1, wn = warp & 1;
    long rowBase = (long)blockIdx.x * 128;

    for (int p = 0; p < 2; p++) {
        float* A = p ? Aseg : Ain;
        const float* B = p ? Bb : Ba;

        for (int i = tid; i < 128 * 32; i += 256) {
            int r = i >> 5, c = (i & 31) * 4;
            float4 b = ld4(B + r * 128 + c);
            float* d = Bs + r * ARB + c;
            d[0] = tf32r(b.x); d[1] = tf32r(b.y); d[2] = tf32r(b.z); d[3] = tf32r(b.w);
        }

        float acc[2][8][4];
#pragma unroll
        for (int tm = 0; tm < 2; tm++)
#pragma unroll
            for (int nt = 0; nt < 8; nt++)
#pragma unroll
                for (int j = 0; j < 4; j++) acc[tm][nt][j] = 0.f;

        int lr = tid >> 1, lkh = (tid & 1) * 16;

        for (int kt = 0; kt < 128; kt += 32) {
            const float* ap = A + (rowBase + lr) * 128 + kt + lkh;
#pragma unroll
            for (int j = 0; j < 4; j++) {
                float4 a = ld4(ap + j * 4);
                int k0 = lkh + j * 4;
                As[(k0 + 0) * ARB + lr] = tf32r(a.x);
                As[(k0 + 1) * ARB + lr] = tf32r(a.y);
                As[(k0 + 2) * ARB + lr] = tf32r(a.z);
                As[(k0 + 3) * ARB + lr] = tf32r(a.w);
            }
            __syncthreads();

#pragma unroll
            for (int ks = 0; ks < 4; ks++) {
                uint32_t af[2][4];
#pragma unroll
                for (int tm = 0; tm < 2; tm++) {
                    int rr = wm * 32 + tm * 16 + gid;
                    const float* a0p = As + (ks * 8 + tig) * ARB + rr;
                    const float* a1p = As + (ks * 8 + tig + 4) * ARB + rr;
                    af[tm][0] = __float_as_uint(a0p[0]);
                    af[tm][1] = __float_as_uint(a0p[8]);
                    af[tm][2] = __float_as_uint(a1p[0]);
                    af[tm][3] = __float_as_uint(a1p[8]);
                }
#pragma unroll
                for (int nt = 0; nt < 8; nt++) {
                    int cc = wn * 64 + nt * 8 + gid;
                    uint32_t b0 = __float_as_uint(Bs[(kt + ks * 8 + tig) * ARB + cc]);
                    uint32_t b1 = __float_as_uint(Bs[(kt + ks * 8 + tig + 4) * ARB + cc]);
#pragma unroll
                    for (int tm = 0; tm < 2; tm++)
                        MMA_TF32(acc[tm][nt], af[tm][0], af[tm][1], af[tm][2], af[tm][3], b0, b1);
                }
            }
            __syncthreads();
        }

#pragma unroll
        for (int tm = 0; tm < 2; tm++) {
            long r0 = rowBase + wm * 32 + tm * 16 + gid;
#pragma unroll
            for (int nt = 0; nt < 8; nt++) {
                int cc = wn * 64 + nt * 8 + tig * 2;
                *(float2*)(A + r0 * 128 + cc)       = make_float2(acc[tm][nt][0], acc[tm][nt][1]);
                *(float2*)(A + (r0 + 8) * 128 + cc) = make_float2(acc[tm][nt][2], acc[tm][nt][3]);
            }
        }
        __syncthreads();
    }
}

// ---------------- GN helpers ----------------
__device__ __forceinline__ void gn_stats(float4 x, float& mean, float& kinv) {
    float s  = x.x + x.y + x.z + x.w;
    float sq = x.x * x.x + x.y * x.y + x.z * x.z + x.w * x.w;
    s  = wsum(s)  * (1.f / 128.f);
    sq = wsum(sq) * (1.f / 128.f);
    mean = s;
    float var = sq - s * s;
    kinv = rsqrtf(var + 1e-5f);
}

__global__ __launch_bounds__(256) void enc2_kernel(
    const float* __restrict__ A, const float* __restrict__ gA, const float* __restrict__ bA,
    const float* __restrict__ Bv, const float* __restrict__ gB, const float* __restrict__ bB,
    float* __restrict__ feat)
{
    int row = blockIdx.x * 8 + (threadIdx.x >> 5);
    if (row >= NN) return;
    int lane = threadIdx.x & 31;
    int c = lane * 4;
    float4 a = ld4(&A[(long)row * 128 + c]);
    float4 b = ld4(&Bv[(long)row * 128 + c]);
    float ma, ka, mb, kb;
    gn_stats(a, ma, ka);
    gn_stats(b, mb, kb);
    float4 ga = ld4(gA + c), ba = ld4(bA + c);
    float4 gb = ld4(gB + c), bb = ld4(bB + c);
    float4 o;
    o.x = fmaxf((a.x - ma) * ka * ga.x + ba.x + (b.x - mb) * kb * gb.x + bb.x, 0.f);
    o.y = fmaxf((a.y - ma) * ka * ga.y + ba.y + (b.y - mb) * kb * gb.y + bb.y, 0.f);
    o.z = fmaxf((a.z - ma) * ka * ga.z + ba.z + (b.z - mb) * kb * gb.z + bb.z, 0.f);
    o.w = fmaxf((a.w - ma) * ka * ga.w + ba.w + (b.w - mb) * kb * gb.w + bb.w, 0.f);
    *(float4*)&feat[(long)row * 128 + c] = o;
}

// ---------------- fused layer GEMM helper (16 warps, 4x4 grid, warp tile 32x32) ----------------
template<bool CVT>
__device__ __forceinline__ void gemm_tile(const float* As, const float* Bs,
                                          float acc[2][4][4], int wm, int wn, int gid, int tig)
{
#pragma unroll
    for (int ks = 0; ks < 16; ks++) {
        int kk = ks * 8;
        uint32_t af[2][4];
#pragma unroll
        for (int tm = 0; tm < 2; tm++) {
            int rr = wm * 32 + tm * 16 + gid;
            float a0 = As[rr * ARA + kk + tig];
            float a1 = As[(rr + 8) * ARA + kk + tig];
            float a2 = As[rr * ARA + kk + tig + 4];
            float a3 = As[(rr + 8) * ARA + kk + tig + 4];
            if (CVT) { a0 = tf32r(a0); a1 = tf32r(a1); a2 = tf32r(a2); a3 = tf32r(a3); }
            af[tm][0] = __float_as_uint(a0);
            af[tm][1] = __float_as_uint(a1);
            af[tm][2] = __float_as_uint(a2);
            af[tm][3] = __float_as_uint(a3);
        }
#pragma unroll
        for (int nt = 0; nt < 4; nt++) {
            int cc = wn * 32 + nt * 8 + gid;
            uint32_t b0 = __float_as_uint(Bs[(kk + tig) * ARB + cc]);
            uint32_t b1 = __float_as_uint(Bs[(kk + tig + 4) * ARB + cc]);
#pragma unroll
            for (int tm = 0; tm < 2; tm++)
                MMA_TF32(acc[tm][nt], af[tm][0], af[tm][1], af[tm][2], af[tm][3], b0, b1);
        }
    }
}

__device__ __forceinline__ void stage_acc(float* As, float acc[2][4][4],
                                          int wm, int wn, int gid, int tig)
{
#pragma unroll
    for (int tm = 0; tm < 2; tm++) {
        int r0 = wm * 32 + tm * 16 + gid;
#pragma unroll
        for (int nt = 0; nt < 4; nt++) {
            int cc = wn * 32 + nt * 8 + tig * 2;
            *(float2*)(As + r0 * ARA + cc)       = make_float2(acc[tm][nt][0], acc[tm][nt][1]);
            *(float2*)(As + (r0 + 8) * ARA + cc) = make_float2(acc[tm][nt][2], acc[tm][nt][3]);
        }
    }
}

// ---------------- fused layer kernel: gather-sum + 15 GEMMs + post, no atomics ----------------
__global__ __launch_bounds__(512) void fuse_kernel(
    const float* __restrict__ featIn, float* __restrict__ featOut,
    const float* __restrict__ pre_w, const float* __restrict__ suc_w,
    const float* __restrict__ left_w, const float* __restrict__ right_w,
    const float* __restrict__ ctr_w, const float* __restrict__ ctr2_w,
    const float* __restrict__ ng, const float* __restrict__ nb,
    const float* __restrict__ g2, const float* __restrict__ b2,
    float* __restrict__ dout)
{
    extern __shared__ float sm[];
    float* As = sm;               // [128][ARA] gather tile / staging
    float* Bs = sm + 128 * ARA;   // [128][ARB] weight tile

    int tid = threadIdx.x, lane = tid & 31, warp = tid >> 5;
    int gid = lane >> 2, tig = lane & 3;
    int wm = warp >> 2, wn = warp & 3;
    long rowBase = (long)blockIdx.x * 128;
    int wrow = warp * 8;          // this warp's 8 A-rows

    // prefetch B(0)
    float4 bp[8];
#pragma unroll
    for (int j = 0; j < 8; j++) bp[j] = ld4(pre_w + (tid + j * 512) * 4);

    float acc[2][4][4];
#pragma unroll
    for (int tm = 0; tm < 2; tm++)
#pragma unroll
        for (int nt = 0; nt < 4; nt++)
#pragma unroll
            for (int j = 0; j < 4; j++) acc[tm][nt][j] = 0.f;

    for (int t = 0; t < 15; t++) {
        // commit B(t) regs -> Bs (tf32)
#pragma unroll
        for (int j = 0; j < 8; j++) {
            int idx = tid + j * 512;
            int k = idx >> 5, n = (idx & 31) * 4;
            float4 c;
            c.x = tf32r(bp[j].x); c.y = tf32r(bp[j].y);
            c.z = tf32r(bp[j].z); c.w = tf32r(bp[j].w);
            *(float4*)(Bs + k * ARB + n) = c;
        }

        // gather A(t): each warp owns 8 rows, processed in 2 groups of 4
        if (t < 14) {
            const int tb = t * NPAD;
#pragma unroll
            for (int grp = 0; grp < 2; grp++) {
                int cN[4], eb[4];
#pragma unroll
                for (int j = 0; j < 4; j++) {
                    int u = (int)rowBase + wrow + grp * 4 + j;
                    int b = tb + u;
                    int c = __ldg(&g_cnt3[b]);
                    cN[j] = (c > CAP3) ? CAP3 : c;
                    eb[j] = b * CAP3;
                }
                int v0[4], v1[4];
#pragma unroll
                for (int j = 0; j < 4; j++) v0[j] = (cN[j] > 0) ? __ldg(&g_edg3[eb[j]]) : 0;
#pragma unroll
                for (int j = 0; j < 4; j++) v1[j] = (cN[j] > 1) ? __ldg(&g_edg3[eb[j] + 1]) : 0;
                float4 a[4], d[4];
#pragma unroll
                for (int j = 0; j < 4; j++)
                    a[j] = (cN[j] > 0) ? ld4(featIn + (long)v0[j] * 128 + lane * 4)
                                       : make_float4(0.f, 0.f, 0.f, 0.f);
#pragma unroll
                for (int j = 0; j < 4; j++)
                    d[j] = (cN[j] > 1) ? ld4(featIn + (long)v1[j] * 128 + lane * 4)
                                       : make_float4(0.f, 0.f, 0.f, 0.f);
#pragma unroll
                for (int j = 0; j < 4; j++) {
                    a[j].x += d[j].x; a[j].y += d[j].y; a[j].z += d[j].z; a[j].w += d[j].w;
                }
#pragma unroll
                for (int j = 0; j < 4; j++) {
                    for (int e = 2; e < cN[j]; e++) {
                        int v = __ldg(&g_edg3[eb[j] + e]);
                        float4 f = ld4(featIn + (long)v * 128 + lane * 4);
                        a[j].x += f.x; a[j].y += f.y; a[j].z += f.z; a[j].w += f.w;
                    }
                }
#pragma unroll
                for (int j = 0; j < 4; j++)
                    *(float4*)(As + (wrow + grp * 4 + j) * ARA + lane * 4) = a[j];
            }
        } else {
            // t == 14: A = featIn rows (ctr term)
#pragma unroll
            for (int j = 0; j < 8; j++)
                *(float4*)(As + (wrow + j) * ARA + lane * 4) =
                    ld4(featIn + (rowBase + wrow + j) * 128 + lane * 4);
        }
        __syncthreads();

        // prefetch B(t+1)
        {
            int tn = t + 1;
            const float* Bn;
            if (tn < 6)        Bn = pre_w + tn * 16384;
            else if (tn < 12)  Bn = suc_w + (tn - 6) * 16384;
            else if (tn == 12) Bn = left_w;
            else if (tn == 13) Bn = right_w;
            else if (tn == 14) Bn = ctr_w;
            else               Bn = ctr2_w;
#pragma unroll
            for (int j = 0; j < 8; j++) bp[j] = ld4(Bn + (tid + j * 512) * 4);
        }

        // GEMM(t): acc += A_t @ B_t  (cvt a-frags: As holds raw fp32 sums)
        gemm_tile<true>(As, Bs, acc, wm, wn, gid, tig);
        __syncthreads();
    }

    // ---- fused post ----
    // stage temp tile -> As
    stage_acc(As, acc, wm, wn, gid, tig);
    __syncthreads();

    // GN1 + relu in place (tf32-rounded), commit ctr2_w (in bp) -> Bs
#pragma unroll
    for (int j = 0; j < 8; j++) {
        int idx = tid + j * 512;
        int k = idx >> 5, n = (idx & 31) * 4;
        float4 c;
        c.x = tf32r(bp[j].x); c.y = tf32r(bp[j].y);
        c.z = tf32r(bp[j].z); c.w = tf32r(bp[j].w);
        *(float4*)(Bs + k * ARB + n) = c;
    }
#pragma unroll
    for (int j = 0; j < 8; j++) {
        int r = wrow + j;
        int c = lane * 4;
        float4 x = ld4(As + r * ARA + c);
        float m, k;
        gn_stats(x, m, k);
        float4 gg = ld4(ng + c), bb = ld4(nb + c);
        float4 o;
        o.x = tf32r(fmaxf((x.x - m) * k * gg.x + bb.x, 0.f));
        o.y = tf32r(fmaxf((x.y - m) * k * gg.y + bb.y, 0.f));
        o.z = tf32r(fmaxf((x.z - m) * k * gg.z + bb.z, 0.f));
        o.w = tf32r(fmaxf((x.w - m) * k * gg.w + bb.w, 0.f));
        *(float4*)(As + r * ARA + c) = o;
    }
    __syncthreads();

    // GEMM2: acc = GN1(temp) @ ctr2_w
#pragma unroll
    for (int tm = 0; tm < 2; tm++)
#pragma unroll
        for (int nt = 0; nt < 4; nt++)
#pragma unroll
            for (int j = 0; j < 4; j++) acc[tm][nt][j] = 0.f;
    gemm_tile<false>(As, Bs, acc, wm, wn, gid, tig);
    __syncthreads();

    stage_acc(As, acc, wm, wn, gid, tig);
    __syncthreads();

    // GN2 + residual + relu -> featOut (+dout)
#pragma unroll
    for (int j = 0; j < 8; j++) {
        int r = wrow + j;
        int c = lane * 4;
        float4 x = ld4(As + r * ARA + c);
        float m, k;
        gn_stats(x, m, k);
        float4 gg = ld4(g2 + c), bb = ld4(b2 + c);
        long grow = rowBase + r;
        float4 old = ld4(featIn + grow * 128 + c);
        float4 o;
        o.x = fmaxf((x.x - m) * k * gg.x + bb.x + old.x, 0.f);
        o.y = fmaxf((x.y - m) * k * gg.y + bb.y + old.y, 0.f);
        o.z = fmaxf((x.z - m) * k * gg.z + bb.z + old.z, 0.f);
        o.w = fmaxf((x.w - m) * k * gg.w + bb.w + old.w, 0.f);
        *(float4*)(featOut + grow * 128 + c) = o;
        if (dout && grow < NN) *(float4*)(dout + grow * 128 + c) = o;
    }
}

// ---------------- host launcher ----------------
extern "C" void kernel_launch(void* const* d_in, const int* in_sizes, int n_in,
                              void* d_out, int out_size)
{
    const float* ctrs   = (const float*)d_in[0];
    const float* feats  = (const float*)d_in[1];
    const float* w_in1  = (const float*)d_in[2];
    const float* b_in1  = (const float*)d_in[3];
    const float* w_in2  = (const float*)d_in[4];
    const float* g_in   = (const float*)d_in[5];
    const float* be_in  = (const float*)d_in[6];
    const float* w_seg1 = (const float*)d_in[7];
    const float* b_seg1 = (const float*)d_in[8];
    const float* w_seg2 = (const float*)d_in[9];
    const float* g_seg  = (const float*)d_in[10];
    const float* be_seg = (const float*)d_in[11];
    const float* ctr_w  = (const float*)d_in[12];
    const float* pre_w  = (const float*)d_in[13];
    const float* suc_w  = (const float*)d_in[14];
    const float* left_w = (const float*)d_in[15];
    const float* right_w= (const float*)d_in[16];
    const float* norm_g = (const float*)d_in[17];
    const float* norm_b = (const float*)d_in[18];
    const float* ctr2_w = (const float*)d_in[19];
    const float* ctr2_g = (const float*)d_in[20];
    const float* ctr2_b = (const float*)d_in[21];
    const int* pre_u  = (const int*)d_in[22];
    const int* pre_v  = (const int*)d_in[23];
    const int* suc_u  = (const int*)d_in[24];
    const int* suc_v  = (const int*)d_in[25];
    const int* left_u = (const int*)d_in[26];
    const int* left_v = (const int*)d_in[27];
    const int* right_u= (const int*)d_in[28];
    const int* right_v= (const int*)d_in[29];

    float *featA, *featB, *tmp;
    int *cnt3;
    cudaGetSymbolAddress((void**)&featA, g_feat);
    cudaGetSymbolAddress((void**)&featB, g_y);
    cudaGetSymbolAddress((void**)&tmp,   g_tmp);
    cudaGetSymbolAddress((void**)&cnt3,  g_cnt3);

    const int MAT = 128 * 128;
    const int SMEM_GEMM = 160 * ARB * 4;                    // 87040
    const int SMEM_FUSE = (128 * ARA + 128 * ARB) * 4;      // 137216
    const int TOT = 12 * EE + 2 * EE2;
    const int EB = (TOT + 255) / 256;

    static bool attr_set = false;
    if (!attr_set) {
        cudaFuncSetAttribute(enc_gemm2_kernel, cudaFuncAttributeMaxDynamicSharedMemorySize, SMEM_GEMM);
        cudaFuncSetAttribute(fuse_kernel,      cudaFuncAttributeMaxDynamicSharedMemorySize, SMEM_FUSE);
        attr_set = true;
    }

    // edge CSR build (per-u buckets)
    cudaMemsetAsync(cnt3, 0, NTYPE * NPAD * sizeof(int));
    place_kernel<<<EB, 256>>>(pre_u, pre_v, suc_u, suc_v, left_u, left_v, right_u, right_v);

    // encoders
    enc1_kernel<<<(NN * 32) / 256, 256>>>(ctrs, feats, w_in1, b_in1, w_seg1, b_seg1, tmp, featB);
    enc_gemm2_kernel<<<NBLK, 256, SMEM_GEMM>>>(tmp, w_in2, featB, w_seg2);
    enc2_kernel<<<NN / 8, 256>>>(tmp, g_in, be_in, featB, g_seg, be_seg, featA);

    // fused layers (ping-pong feat buffers)
    for (int i = 0; i < LL; i++) {
        const float* fin  = (i & 1) ? featB : featA;
        float*       fout = (i & 1) ? featA : featB;
        fuse_kernel<<<NBLK, 512, SMEM_FUSE>>>(
            fin, fout,
            pre_w + (size_t)i * SS * MAT, suc_w + (size_t)i * SS * MAT,
            left_w + (size_t)i * MAT, right_w + (size_t)i * MAT,
            ctr_w + (size_t)i * MAT, ctr2_w + (size_t)i * MAT,
            norm_g + i * 128, norm_b + i * 128,
            ctr2_g + i * 128, ctr2_b + i * 128,
            (i == LL - 1) ? (float*)d_out : nullptr);
    }
}

// round 8
// speedup vs baseline: 1.3681x; 1.3681x over previous
#include <cuda_runtime.h>
#include <cuda_fp16.h>
#include <cstdint>

#define NN 200000
#define NPAD 200064     // 1563 * 128
#define DD 128
#define EE 200000
#define EE2 20000
#define SS 6
#define LL 4
#define NBLK 1563
#define ARB 136         // tf32 encoder smem stride
#define S2  136         // fp16 half2 smem stride (uint32 units)
#define CSTR 132        // C staging stride: 132*4=528B, 16B-aligned rows
#define NTYPE 14
#define NBUCK (NTYPE * NBLK)
#define TOTAL_E (12 * EE + 2 * EE2)
#define CAP1 256
#define CAP2 64
#define EDGESZ (12 * NBLK * CAP1 + 2 * NBLK * CAP2)

// fuse smem (bytes): As2 64*136*4=34816 | Bs2 34816 | Cs 128*132*4=67584
#define F_A 0
#define F_B 34816
#define F_C 69632
#define SMEM_FUSE2 (69632 + 67584)    // 137216
// post smem: As2+Bs2; Cs (67584) unioned over the same region
#define SMEM_POST 69632

// ---------------- device scratch ----------------
__device__ float g_feat[NPAD * DD];
__device__ float g_y   [NPAD * DD];
__device__ float g_tmp [NPAD * DD];
__device__ int   g_cnt [NBUCK];
__device__ int   g_edges[EDGESZ];

__device__ __forceinline__ float4 ld4(const float* p) { return *(const float4*)(p); }

__device__ __forceinline__ float tf32r(float x) {
    float y;
    asm("cvt.rna.tf32.f32 %0, %1;" : "=f"(y) : "f"(x));
    return y;
}

// pack (lo=first-k, hi=second-k) into b32 f16x2
__device__ __forceinline__ uint32_t h2(float lo, float hi) {
    uint32_t r;
    asm("cvt.rn.f16x2.f32 %0, %1, %2;" : "=r"(r) : "f"(hi), "f"(lo));
    return r;
}

__device__ __forceinline__ float wsum(float s) {
#pragma unroll
    for (int o = 16; o; o >>= 1) s += __shfl_xor_sync(0xffffffffu, s, o);
    return s;
}

__device__ __forceinline__ void redv4(float* p, float4 y) {
    asm volatile("red.global.add.v4.f32 [%0], {%1,%2,%3,%4};"
                 :: "l"(p), "f"(y.x), "f"(y.y), "f"(y.z), "f"(y.w) : "memory");
}

#define MMA_TF32(acc, a0, a1, a2, a3, b0, b1) \
    asm volatile( \
        "mma.sync.aligned.m16n8k8.row.col.f32.tf32.tf32.f32 " \
        "{%0,%1,%2,%3}, {%4,%5,%6,%7}, {%8,%9}, {%0,%1,%2,%3};\n" \
        : "+f"((acc)[0]), "+f"((acc)[1]), "+f"((acc)[2]), "+f"((acc)[3]) \
        : "r"(a0), "r"(a1), "r"(a2), "r"(a3), "r"(b0), "r"(b1))

#define MMA_F16(acc, a0, a1, a2, a3, b0, b1) \
    asm volatile( \
        "mma.sync.aligned.m16n8k16.row.col.f32.f16.f16.f32 " \
        "{%0,%1,%2,%3}, {%4,%5,%6,%7}, {%8,%9}, {%0,%1,%2,%3};\n" \
        : "+f"((acc)[0]), "+f"((acc)[1]), "+f"((acc)[2]), "+f"((acc)[3]) \
        : "r"(a0), "r"(a1), "r"(a2), "r"(a3), "r"(b0), "r"(b1))

// ---------------- edge buckets (type, v-block) ----------------
__global__ void place_kernel(const int* __restrict__ pre_u, const int* __restrict__ pre_v,
                             const int* __restrict__ suc_u, const int* __restrict__ suc_v,
                             const int* __restrict__ left_u, const int* __restrict__ left_v,
                             const int* __restrict__ right_u, const int* __restrict__ right_v)
{
    int idx = blockIdx.x * 256 + threadIdx.x;
    int t, u, v;
    if (idx < 6 * EE)            { t = idx / EE; u = pre_u[idx]; v = pre_v[idx]; }
    else if (idx < 12 * EE)      { int j = idx - 6 * EE; t = idx / EE; u = suc_u[j]; v = suc_v[j]; }
    else if (idx < 12 * EE + EE2){ int j = idx - 12 * EE; t = 12; u = left_u[j]; v = left_v[j]; }
    else if (idx < TOTAL_E)      { int j = idx - 12 * EE - EE2; t = 13; u = right_u[j]; v = right_v[j]; }
    else return;
    int vb = v >> 7;
    int b = t * NBLK + vb;
    int cap  = (t < 12) ? CAP1 : CAP2;
    int base = (t < 12) ? b * CAP1 : (12 * NBLK * CAP1 + ((t - 12) * NBLK + vb) * CAP2);
    int pos = atomicAdd(&g_cnt[b], 1);
    if (pos < cap) g_edges[base + pos] = u | ((v & 127) << 18);
}

// ---------------- encoder stage 1 ----------------
__global__ __launch_bounds__(256) void enc1_kernel(
    const float* __restrict__ ctrs, const float* __restrict__ feats,
    const float* __restrict__ w_in1, const float* __restrict__ b_in1,
    const float* __restrict__ w_seg1, const float* __restrict__ b_seg1,
    float* __restrict__ h_in, float* __restrict__ h_seg)
{
    int idx = blockIdx.x * blockDim.x + threadIdx.x;
    int n = idx >> 5;
    if (n >= NN) return;
    int c = (idx & 31) * 4;

    float c0 = __ldg(&ctrs[2 * n]),  c1 = __ldg(&ctrs[2 * n + 1]);
    float f0 = __ldg(&feats[2 * n]), f1 = __ldg(&feats[2 * n + 1]);

    float4 wi0 = ld4(w_in1 + c), wi1 = ld4(w_in1 + DD + c), bi = ld4(b_in1 + c);
    float4 ws0 = ld4(w_seg1 + c), ws1 = ld4(w_seg1 + DD + c), bs = ld4(b_seg1 + c);

    float4 hi, hs;
    hi.x = fmaxf(c0 * wi0.x + c1 * wi1.x + bi.x, 0.f);
    hi.y = fmaxf(c0 * wi0.y + c1 * wi1.y + bi.y, 0.f);
    hi.z = fmaxf(c0 * wi0.z + c1 * wi1.z + bi.z, 0.f);
    hi.w = fmaxf(c0 * wi0.w + c1 * wi1.w + bi.w, 0.f);
    hs.x = fmaxf(f0 * ws0.x + f1 * ws1.x + bs.x, 0.f);
    hs.y = fmaxf(f0 * ws0.y + f1 * ws1.y + bs.y, 0.f);
    hs.z = fmaxf(f0 * ws0.z + f1 * ws1.z + bs.z, 0.f);
    hs.w = fmaxf(f0 * ws0.w + f1 * ws1.w + bs.w, 0.f);

    *(float4*)&h_in [n * DD + c] = hi;
    *(float4*)&h_seg[n * DD + c] = hs;
}

// ---------------- encoder GEMM pair (tf32 mma.sync, in-place) ----------------
__global__ __launch_bounds__(256, 2) void enc_gemm2_kernel(
    float* __restrict__ Ain, const float* __restrict__ Ba,
    float* __restrict__ Aseg, const float* __restrict__ Bb)
{
    extern __shared__ float sm[];
    float* Bs = sm;
    float* As = sm + 128 * ARB;

    int tid = threadIdx.x, lane = tid & 31, warp = tid >> 5;
    int gid = lane >> 2, tig = lane & 3;
    int wm = warp >> 1, wn = warp & 1;
    long rowBase = (long)blockIdx.x * 128;

    for (int p = 0; p < 2; p++) {
        float* A = p ? Aseg : Ain;
        const float* B = p ? Bb : Ba;

        for (int i = tid; i < 128 * 32; i += 256) {
            int r = i >> 5, c = (i & 31) * 4;
            float4 b = ld4(B + r * 128 + c);
            float* d = Bs + r * ARB + c;
            d[0] = tf32r(b.x); d[1] = tf32r(b.y); d[2] = tf32r(b.z); d[3] = tf32r(b.w);
        }

        float acc[2][8][4];
#pragma unroll
        for (int tm = 0; tm < 2; tm++)
#pragma unroll
            for (int nt = 0; nt < 8; nt++)
#pragma unroll
                for (int j = 0; j < 4; j++) acc[tm][nt][j] = 0.f;

        int lr = tid >> 1, lkh = (tid & 1) * 16;

        for (int kt = 0; kt < 128; kt += 32) {
            const float* ap = A + (rowBase + lr) * 128 + kt + lkh;
#pragma unroll
            for (int j = 0; j < 4; j++) {
                float4 a = ld4(ap + j * 4);
                int k0 = lkh + j * 4;
                As[(k0 + 0) * ARB + lr] = tf32r(a.x);
                As[(k0 + 1) * ARB + lr] = tf32r(a.y);
                As[(k0 + 2) * ARB + lr] = tf32r(a.z);
                As[(k0 + 3) * ARB + lr] = tf32r(a.w);
            }
            __syncthreads();

#pragma unroll
            for (int ks = 0; ks < 4; ks++) {
                uint32_t af[2][4];
#pragma unroll
                for (int tm = 0; tm < 2; tm++) {
                    int rr = wm * 32 + tm * 16 + gid;
                    const float* a0p = As + (ks * 8 + tig) * ARB + rr;
                    const float* a1p = As + (ks * 8 + tig + 4) * ARB + rr;
                    af[tm][0] = __float_as_uint(a0p[0]);
                    af[tm][1] = __float_as_uint(a0p[8]);
                    af[tm][2] = __float_as_uint(a1p[0]);
                    af[tm][3] = __float_as_uint(a1p[8]);
                }
#pragma unroll
                for (int nt = 0; nt < 8; nt++) {
                    int cc = wn * 64 + nt * 8 + gid;
                    uint32_t b0 = __float_as_uint(Bs[(kt + ks * 8 + tig) * ARB + cc]);
                    uint32_t b1 = __float_as_uint(Bs[(kt + ks * 8 + tig + 4) * ARB + cc]);
#pragma unroll
                    for (int tm = 0; tm < 2; tm++)
                        MMA_TF32(acc[tm][nt], af[tm][0], af[tm][1], af[tm][2], af[tm][3], b0, b1);
                }
            }
            __syncthreads();
        }

#pragma unroll
        for (int tm = 0; tm < 2; tm++) {
            long r0 = rowBase + wm * 32 + tm * 16 + gid;
#pragma unroll
            for (int nt = 0; nt < 8; nt++) {
                int cc = wn * 64 + nt * 8 + tig * 2;
                *(float2*)(A + r0 * 128 + cc)       = make_float2(acc[tm][nt][0], acc[tm][nt][1]);
                *(float2*)(A + (r0 + 8) * 128 + cc) = make_float2(acc[tm][nt][2], acc[tm][nt][3]);
            }
        }
        __syncthreads();
    }
}

// ---------------- GN helpers ----------------
__device__ __forceinline__ void gn_stats(float4 x, float& mean, float& kinv) {
    float s  = x.x + x.y + x.z + x.w;
    float sq = x.x * x.x + x.y * x.y + x.z * x.z + x.w * x.w;
    s  = wsum(s)  * (1.f / 128.f);
    sq = wsum(sq) * (1.f / 128.f);
    mean = s;
    float var = sq - s * s;
    kinv = rsqrtf(var + 1e-5f);
}

// enc2: feat = relu(gn(A) + gn(B)); zero A rows (tmp) for iter 0
__global__ __launch_bounds__(256) void enc2_kernel(
    float* __restrict__ A, const float* __restrict__ gA, const float* __restrict__ bA,
    const float* __restrict__ Bv, const float* __restrict__ gB, const float* __restrict__ bB,
    float* __restrict__ feat)
{
    int row = blockIdx.x * 8 + (threadIdx.x >> 5);
    if (row >= NN) return;
    int lane = threadIdx.x & 31;
    int c = lane * 4;
    float4 a = ld4(&A[(long)row * 128 + c]);
    float4 b = ld4(&Bv[(long)row * 128 + c]);
    float ma, ka, mb, kb;
    gn_stats(a, ma, ka);
    gn_stats(b, mb, kb);
    float4 ga = ld4(gA + c), ba = ld4(bA + c);
    float4 gb = ld4(gB + c), bb = ld4(bB + c);
    float4 o;
    o.x = fmaxf((a.x - ma) * ka * ga.x + ba.x + (b.x - mb) * kb * gb.x + bb.x, 0.f);
    o.y = fmaxf((a.y - ma) * ka * ga.y + ba.y + (b.y - mb) * kb * gb.y + bb.y, 0.f);
    o.z = fmaxf((a.z - ma) * ka * ga.z + ba.z + (b.z - mb) * kb * gb.z + bb.z, 0.f);
    o.w = fmaxf((a.w - ma) * ka * ga.w + ba.w + (b.w - mb) * kb * gb.w + bb.w, 0.f);
    *(float4*)&feat[(long)row * 128 + c] = o;
    *(float4*)&A   [(long)row * 128 + c] = make_float4(0.f, 0.f, 0.f, 0.f);
}

// ---------------- fused message-passing kernel (fp16 mma, 512 threads) ----------------
__global__ __launch_bounds__(512) void fuse_kernel(
    const float* __restrict__ featIn, float* __restrict__ temp,
    const float* __restrict__ pre_w, const float* __restrict__ suc_w,
    const float* __restrict__ left_w, const float* __restrict__ right_w,
    const float* __restrict__ ctr_w)
{
    extern __shared__ char smc[];
    uint32_t* As2 = (uint32_t*)(smc + F_A);   // [64 kpair][S2] half2
    uint32_t* Bs2 = (uint32_t*)(smc + F_B);   // [64 kpair][S2] half2
    float*    Cs  = (float*)(smc + F_C);      // [128][CSTR]

    int tid = threadIdx.x, lane = tid & 31, warp = tid >> 5;
    int gid = lane >> 2, tig = lane & 3;
    int wm = warp >> 2, wn = warp & 3;       // 4x4 warp grid, warp tile 32x32
    long rowBase = (long)blockIdx.x * 128;

    // load A tile once (fp16 pairs along k)
    {
        int r = tid >> 2, q = tid & 3;
        const float* ap = featIn + (rowBase + r) * 128 + q * 32;
#pragma unroll
        for (int j = 0; j < 8; j++) {
            float4 a = ld4(ap + j * 4);
            int kp = q * 16 + j * 2;
            As2[(kp + 0) * S2 + r] = h2(a.x, a.y);
            As2[(kp + 1) * S2 + r] = h2(a.z, a.w);
        }
    }

    // prefetch B(0): 64 kpairs x 32 colgroups = 2048 items, 4/thread
    float4 blo[4], bhi[4];
#pragma unroll
    for (int j = 0; j < 4; j++) {
        int idx = tid + j * 512;
        int kp = idx >> 5, cg = (idx & 31) * 4;
        blo[j] = ld4(pre_w + (2 * kp) * 128 + cg);
        bhi[j] = ld4(pre_w + (2 * kp + 1) * 128 + cg);
    }

    __syncthreads();

    for (int t = 0; t < 15; t++) {
        // commit B(t) -> Bs2
#pragma unroll
        for (int j = 0; j < 4; j++) {
            int idx = tid + j * 512;
            int kp = idx >> 5, cg = (idx & 31) * 4;
            uint4 v;
            v.x = h2(blo[j].x, bhi[j].x);
            v.y = h2(blo[j].y, bhi[j].y);
            v.z = h2(blo[j].z, bhi[j].z);
            v.w = h2(blo[j].w, bhi[j].w);
            *(uint4*)(Bs2 + kp * S2 + cg) = v;
        }
        __syncthreads();   // Bs2 visible; scatter(t-1) done reading Cs

        // prefetch B(t+1)
        if (t < 14) {
            int tn = t + 1;
            const float* Bn;
            if (tn < 6)        Bn = pre_w + tn * 16384;
            else if (tn < 12)  Bn = suc_w + (tn - 6) * 16384;
            else if (tn == 12) Bn = left_w;
            else if (tn == 13) Bn = right_w;
            else               Bn = ctr_w;
#pragma unroll
            for (int j = 0; j < 4; j++) {
                int idx = tid + j * 512;
                int kp = idx >> 5, cg = (idx & 31) * 4;
                blo[j] = ld4(Bn + (2 * kp) * 128 + cg);
                bhi[j] = ld4(Bn + (2 * kp + 1) * 128 + cg);
            }
        }

        float acc[2][4][4];
#pragma unroll
        for (int tm = 0; tm < 2; tm++)
#pragma unroll
            for (int nt = 0; nt < 4; nt++)
#pragma unroll
                for (int j = 0; j < 4; j++) acc[tm][nt][j] = 0.f;

#pragma unroll
        for (int ks = 0; ks < 8; ks++) {
            int kk = ks * 8;
            uint32_t af[2][4];
#pragma unroll
            for (int tm = 0; tm < 2; tm++) {
                int rr = wm * 32 + tm * 16 + gid;
                const uint32_t* a0p = As2 + (kk + tig) * S2 + rr;
                const uint32_t* a1p = As2 + (kk + tig + 4) * S2 + rr;
                af[tm][0] = a0p[0];
                af[tm][1] = a0p[8];
                af[tm][2] = a1p[0];
                af[tm][3] = a1p[8];
            }
#pragma unroll
            for (int nt = 0; nt < 4; nt++) {
                int cc = wn * 32 + nt * 8 + gid;
                uint32_t b0 = Bs2[(kk + tig) * S2 + cc];
                uint32_t b1 = Bs2[(kk + tig + 4) * S2 + cc];
#pragma unroll
                for (int tm = 0; tm < 2; tm++)
                    MMA_F16(acc[tm][nt], af[tm][0], af[tm][1], af[tm][2], af[tm][3], b0, b1);
            }
        }

        // stage C tile (warp-owned rows)
#pragma unroll
        for (int tm = 0; tm < 2; tm++) {
            int r0 = wm * 32 + tm * 16 + gid;
#pragma unroll
            for (int nt = 0; nt < 4; nt++) {
                int cc = wn * 32 + nt * 8 + tig * 2;
                *(float2*)(Cs + r0 * CSTR + cc)       = make_float2(acc[tm][nt][0], acc[tm][nt][1]);
                *(float2*)(Cs + (r0 + 8) * CSTR + cc) = make_float2(acc[tm][nt][2], acc[tm][nt][3]);
            }
        }
        __syncthreads();

        // scatter from Cs (atomic red)
        if (t < 14) {
            int b = t * NBLK + blockIdx.x;
            int base = (t < 12) ? b * CAP1
                                : (12 * NBLK * CAP1 + ((t - 12) * NBLK + blockIdx.x) * CAP2);
            int cap = (t < 12) ? CAP1 : CAP2;
            int len = g_cnt[b];
            if (len > cap) len = cap;
            for (int e = warp; e < len; e += 16) {
                int pk = __ldg(&g_edges[base + e]);
                int u  = pk & 0x3FFFF;
                int vl = pk >> 18;
                float4 y = *(float4*)(Cs + vl * CSTR + lane * 4);
                redv4(temp + (long)u * 128 + lane * 4, y);
            }
        } else {
            for (int r = warp; r < 128; r += 16) {
                float4 y = *(float4*)(Cs + r * CSTR + lane * 4);
                redv4(temp + (rowBase + r) * 128 + lane * 4, y);
            }
        }
        // no sync: next type's B-commit writes Bs2 then syncs before staging Cs
    }
}

// ---------------- post: fp16 mma; feat = relu(gn2(relu(gn1(tmp)) @ ctr2_w) + feat_old) ----------------
__global__ __launch_bounds__(256, 2) void post_kernel(
    float* __restrict__ tmp, float* __restrict__ feat,
    const float* __restrict__ Bw,
    const float* __restrict__ ng, const float* __restrict__ nb,
    const float* __restrict__ g2, const float* __restrict__ b2,
    float* __restrict__ dout, int zero_tmp)
{
    extern __shared__ char smc[];
    uint32_t* As2 = (uint32_t*)(smc);             // [64][S2] half2
    uint32_t* Bs2 = (uint32_t*)(smc + 34816);     // [64][S2] half2
    float*    Cs  = (float*)(smc);                // staging (union, after GEMM)

    int tid = threadIdx.x, lane = tid & 31, warp = tid >> 5;
    int gid = lane >> 2, tig = lane & 3;
    int wm = warp >> 1, wn = warp & 1;            // 4x2 warp grid, warp tile 32x64
    long rowBase = (long)blockIdx.x * 128;

    // prologue: GN1 + relu -> fp16 pairs into As2; optional zero tmp
    {
        int r = tid >> 1;
        int h = (tid & 1) * 64;
        float* xp = tmp + (rowBase + r) * 128 + h;
        float s = 0.f, sq = 0.f;
        float4 av[16];
#pragma unroll
        for (int j = 0; j < 16; j++) {
            av[j] = ld4(xp + j * 4);
            s  += av[j].x + av[j].y + av[j].z + av[j].w;
            sq += av[j].x * av[j].x + av[j].y * av[j].y + av[j].z * av[j].z + av[j].w * av[j].w;
        }
        s  += __shfl_xor_sync(0xffffffffu, s, 1);
        sq += __shfl_xor_sync(0xffffffffu, sq, 1);
        float mean = s * (1.f / 128.f);
        float kinv = rsqrtf(sq * (1.f / 128.f) - mean * mean + 1e-5f);
        int h2base = h >> 1;
#pragma unroll
        for (int j = 0; j < 16; j++) {
            int k = h + j * 4;
            float4 gg = ld4(ng + k), bb = ld4(nb + k);
            float ox = fmaxf((av[j].x - mean) * kinv * gg.x + bb.x, 0.f);
            float oy = fmaxf((av[j].y - mean) * kinv * gg.y + bb.y, 0.f);
            float oz = fmaxf((av[j].z - mean) * kinv * gg.z + bb.z, 0.f);
            float ow = fmaxf((av[j].w - mean) * kinv * gg.w + bb.w, 0.f);
            As2[(h2base + j * 2 + 0) * S2 + r] = h2(ox, oy);
            As2[(h2base + j * 2 + 1) * S2 + r] = h2(oz, ow);
        }
        if (zero_tmp) {
            float4 z = make_float4(0.f, 0.f, 0.f, 0.f);
#pragma unroll
            for (int j = 0; j < 16; j++) *(float4*)(xp + j * 4) = z;
        }
    }

    // load full B (fp16 pairs): 2048 items, 8/thread
#pragma unroll
    for (int j = 0; j < 8; j++) {
        int idx = tid + j * 256;
        int kp = idx >> 5, cg = (idx & 31) * 4;
        float4 lo = ld4(Bw + (2 * kp) * 128 + cg);
        float4 hi = ld4(Bw + (2 * kp + 1) * 128 + cg);
        uint4 v;
        v.x = h2(lo.x, hi.x);
        v.y = h2(lo.y, hi.y);
        v.z = h2(lo.z, hi.z);
        v.w = h2(lo.w, hi.w);
        *(uint4*)(Bs2 + kp * S2 + cg) = v;
    }
    __syncthreads();

    float acc[2][8][4];
#pragma unroll
    for (int tm = 0; tm < 2; tm++)
#pragma unroll
        for (int nt = 0; nt < 8; nt++)
#pragma unroll
            for (int j = 0; j < 4; j++) acc[tm][nt][j] = 0.f;

#pragma unroll
    for (int ks = 0; ks < 8; ks++) {
        int kk = ks * 8;
        uint32_t af[2][4];
#pragma unroll
        for (int tm = 0; tm < 2; tm++) {
            int rr = wm * 32 + tm * 16 + gid;
            const uint32_t* a0p = As2 + (kk + tig) * S2 + rr;
            const uint32_t* a1p = As2 + (kk + tig + 4) * S2 + rr;
            af[tm][0] = a0p[0];
            af[tm][1] = a0p[8];
            af[tm][2] = a1p[0];
            af[tm][3] = a1p[8];
        }
#pragma unroll
        for (int nt = 0; nt < 8; nt++) {
            int cc = wn * 64 + nt * 8 + gid;
            uint32_t b0 = Bs2[(kk + tig) * S2 + cc];
            uint32_t b1 = Bs2[(kk + tig + 4) * S2 + cc];
#pragma unroll
            for (int tm = 0; tm < 2; tm++)
                MMA_F16(acc[tm][nt], af[tm][0], af[tm][1], af[tm][2], af[tm][3], b0, b1);
        }
    }
    __syncthreads();   // everyone done reading As2/Bs2 before Cs overwrite

    // stage C (fp32) into union region
#pragma unroll
    for (int tm = 0; tm < 2; tm++) {
        int r0 = wm * 32 + tm * 16 + gid;
#pragma unroll
        for (int nt = 0; nt < 8; nt++) {
            int cc = wn * 64 + nt * 8 + tig * 2;
            *(float2*)(Cs + r0 * CSTR + cc)       = make_float2(acc[tm][nt][0], acc[tm][nt][1]);
            *(float2*)(Cs + (r0 + 8) * CSTR + cc) = make_float2(acc[tm][nt][2], acc[tm][nt][3]);
        }
    }
    __syncthreads();

    // epilogue: GN2 + residual + relu
    for (int r = warp; r < 128; r += 8) {
        int c = lane * 4;
        float4 x = *(float4*)(Cs + r * CSTR + c);
        float m, k;
        gn_stats(x, m, k);
        float4 gg = ld4(g2 + c), bb = ld4(b2 + c);
        long grow = rowBase + r;
        float4 old = ld4(feat + grow * 128 + c);
        float4 o;
        o.x = fmaxf((x.x - m) * k * gg.x + bb.x + old.x, 0.f);
        o.y = fmaxf((x.y - m) * k * gg.y + bb.y + old.y, 0.f);
        o.z = fmaxf((x.z - m) * k * gg.z + bb.z + old.z, 0.f);
        o.w = fmaxf((x.w - m) * k * gg.w + bb.w + old.w, 0.f);
        *(float4*)(feat + grow * 128 + c) = o;
        if (dout && grow < NN) *(float4*)(dout + grow * 128 + c) = o;
    }
}

// ---------------- host launcher ----------------
extern "C" void kernel_launch(void* const* d_in, const int* in_sizes, int n_in,
                              void* d_out, int out_size)
{
    const float* ctrs   = (const float*)d_in[0];
    const float* feats  = (const float*)d_in[1];
    const float* w_in1  = (const float*)d_in[2];
    const float* b_in1  = (const float*)d_in[3];
    const float* w_in2  = (const float*)d_in[4];
    const float* g_in   = (const float*)d_in[5];
    const float* be_in  = (const float*)d_in[6];
    const float* w_seg1 = (const float*)d_in[7];
    const float* b_seg1 = (const float*)d_in[8];
    const float* w_seg2 = (const float*)d_in[9];
    const float* g_seg  = (const float*)d_in[10];
    const float* be_seg = (const float*)d_in[11];
    const float* ctr_w  = (const float*)d_in[12];
    const float* pre_w  = (const float*)d_in[13];
    const float* suc_w  = (const float*)d_in[14];
    const float* left_w = (const float*)d_in[15];
    const float* right_w= (const float*)d_in[16];
    const float* norm_g = (const float*)d_in[17];
    const float* norm_b = (const float*)d_in[18];
    const float* ctr2_w = (const float*)d_in[19];
    const float* ctr2_g = (const float*)d_in[20];
    const float* ctr2_b = (const float*)d_in[21];
    const int* pre_u  = (const int*)d_in[22];
    const int* pre_v  = (const int*)d_in[23];
    const int* suc_u  = (const int*)d_in[24];
    const int* suc_v  = (const int*)d_in[25];
    const int* left_u = (const int*)d_in[26];
    const int* left_v = (const int*)d_in[27];
    const int* right_u= (const int*)d_in[28];
    const int* right_v= (const int*)d_in[29];

    float *feat, *tmp, *y;
    int *cnt;
    cudaGetSymbolAddress((void**)&feat, g_feat);
    cudaGetSymbolAddress((void**)&tmp,  g_tmp);
    cudaGetSymbolAddress((void**)&y,    g_y);
    cudaGetSymbolAddress((void**)&cnt,  g_cnt);

    const int MAT = 128 * 128;
    const int SMEM_GEMM = 160 * ARB * 4;   // 87040 (encoder tf32 kernel)
    const int EB = (TOTAL_E + 255) / 256;

    static bool attr_set = false;
    if (!attr_set) {
        cudaFuncSetAttribute(enc_gemm2_kernel, cudaFuncAttributeMaxDynamicSharedMemorySize, SMEM_GEMM);
        cudaFuncSetAttribute(post_kernel,      cudaFuncAttributeMaxDynamicSharedMemorySize, SMEM_POST);
        cudaFuncSetAttribute(fuse_kernel,      cudaFuncAttributeMaxDynamicSharedMemorySize, SMEM_FUSE2);
        attr_set = true;
    }

    cudaMemsetAsync(cnt, 0, NBUCK * sizeof(int));
    place_kernel<<<EB, 256>>>(pre_u, pre_v, suc_u, suc_v, left_u, left_v, right_u, right_v);

    enc1_kernel<<<(NN * 32) / 256, 256>>>(ctrs, feats, w_in1, b_in1, w_seg1, b_seg1, tmp, y);
    enc_gemm2_kernel<<<NBLK, 256, SMEM_GEMM>>>(tmp, w_in2, y, w_seg2);
    enc2_kernel<<<NN / 8, 256>>>(tmp, g_in, be_in, y, g_seg, be_seg, feat);

    for (int i = 0; i < LL; i++) {
        fuse_kernel<<<NBLK, 512, SMEM_FUSE2>>>(
            feat, tmp,
            pre_w + (size_t)i * SS * MAT, suc_w + (size_t)i * SS * MAT,
            left_w + (size_t)i * MAT, right_w + (size_t)i * MAT,
            ctr_w + (size_t)i * MAT);
        post_kernel<<<NBLK, 256, SMEM_POST>>>(
            tmp, feat, ctr2_w + (size_t)i * MAT,
            norm_g + i * 128, norm_b + i * 128,
            ctr2_g + i * 128, ctr2_b + i * 128,
            (i == LL - 1) ? (float*)d_out : nullptr,
            (i < LL - 1) ? 1 : 0);
    }
}

// round 9
// speedup vs baseline: 1.5678x; 1.1459x over previous
#include <cuda_runtime.h>
#include <cuda_fp16.h>
#include <cstdint>

#define NN 200000
#define NPAD 200064     // 1563 * 128
#define DD 128
#define EE 200000
#define EE2 20000
#define SS 6
#define LL 4
#define NBLK 1563
#define ARB 136         // tf32 encoder smem stride
#define S2  136         // fp16 half2 smem stride (uint32 units)
#define CSTR 132        // C staging stride: 528B rows, 16B aligned
#define NTYPE 14
#define NBUCK (NTYPE * NBLK)
#define TOTAL_E (12 * EE + 2 * EE2)
#define CAP1 256
#define CAP2 64
#define EDGESZ (12 * NBLK * CAP1 + 2 * NBLK * CAP2)

#define IMGW (64 * S2)          // uint32 words per prepped B image (8704)
#define IMGB (IMGW * 4)         // 34816 bytes

// fuse smem layout (bytes)
#define F_A   0                         // As2: 34816
#define F_B   34816                     // Bs2 x2: 69632
#define F_C   (34816 + 69632)           // Cs: 67584
#define F_E   (34816 + 69632 + 67584)   // EIX: 12800
#define SMEM_FUSE3 (34816 + 69632 + 67584 + 12800)   // 184832
#define SMEM_POST 69632

// ---------------- device scratch ----------------
__device__ float g_feat[NPAD * DD];
__device__ float g_y   [NPAD * DD];
__device__ float g_tmp [NPAD * DD];
__device__ int   g_cnt [NBUCK];
__device__ int   g_edges[EDGESZ];
__device__ uint32_t g_wimg[60 * IMGW];   // 60 prepped fp16 B images (~8.4MB... 60*8704*4 = 2.09MB)

__device__ __forceinline__ float4 ld4(const float* p) { return *(const float4*)(p); }

__device__ __forceinline__ float tf32r(float x) {
    float y;
    asm("cvt.rna.tf32.f32 %0, %1;" : "=f"(y) : "f"(x));
    return y;
}

// pack (lo=first-k, hi=second-k) into b32 f16x2
__device__ __forceinline__ uint32_t h2(float lo, float hi) {
    uint32_t r;
    asm("cvt.rn.f16x2.f32 %0, %1, %2;" : "=r"(r) : "f"(hi), "f"(lo));
    return r;
}

__device__ __forceinline__ float wsum(float s) {
#pragma unroll
    for (int o = 16; o; o >>= 1) s += __shfl_xor_sync(0xffffffffu, s, o);
    return s;
}

__device__ __forceinline__ void redv4(float* p, float4 y) {
    asm volatile("red.global.add.v4.f32 [%0], {%1,%2,%3,%4};"
                 :: "l"(p), "f"(y.x), "f"(y.y), "f"(y.z), "f"(y.w) : "memory");
}

__device__ __forceinline__ uint32_t smem_u32(const void* p) {
    uint32_t a;
    asm("{ .reg .u64 t; cvta.to.shared.u64 t, %1; cvt.u32.u64 %0, t; }" : "=r"(a) : "l"(p));
    return a;
}

__device__ __forceinline__ void cpa16(uint32_t dst, const void* src) {
    asm volatile("cp.async.cg.shared.global [%0], [%1], 16;" :: "r"(dst), "l"(src));
}
__device__ __forceinline__ void cp_commit() {
    asm volatile("cp.async.commit_group;" ::: "memory");
}
template<int N>
__device__ __forceinline__ void cp_wait() {
    asm volatile("cp.async.wait_group %0;" :: "n"(N) : "memory");
}

#define MMA_TF32(acc, a0, a1, a2, a3, b0, b1) \
    asm volatile( \
        "mma.sync.aligned.m16n8k8.row.col.f32.tf32.tf32.f32 " \
        "{%0,%1,%2,%3}, {%4,%5,%6,%7}, {%8,%9}, {%0,%1,%2,%3};\n" \
        : "+f"((acc)[0]), "+f"((acc)[1]), "+f"((acc)[2]), "+f"((acc)[3]) \
        : "r"(a0), "r"(a1), "r"(a2), "r"(a3), "r"(b0), "r"(b1))

#define MMA_F16(acc, a0, a1, a2, a3, b0, b1) \
    asm volatile( \
        "mma.sync.aligned.m16n8k16.row.col.f32.f16.f16.f32 " \
        "{%0,%1,%2,%3}, {%4,%5,%6,%7}, {%8,%9}, {%0,%1,%2,%3};\n" \
        : "+f"((acc)[0]), "+f"((acc)[1]), "+f"((acc)[2]), "+f"((acc)[3]) \
        : "r"(a0), "r"(a1), "r"(a2), "r"(a3), "r"(b0), "r"(b1))

// ---------------- weight prep: fp32 W[k][n] -> fp16x2 image [kpair][S2] ----------------
__global__ __launch_bounds__(256) void prep_kernel(
    const float* __restrict__ pre_w, const float* __restrict__ suc_w,
    const float* __restrict__ left_w, const float* __restrict__ right_w,
    const float* __restrict__ ctr_w)
{
    int m = blockIdx.x;              // 0..59
    int i = m / 15, t = m % 15;
    const float* W;
    if (t < 6)        W = pre_w  + (size_t)(i * 6 + t) * 16384;
    else if (t < 12)  W = suc_w  + (size_t)(i * 6 + (t - 6)) * 16384;
    else if (t == 12) W = left_w  + (size_t)i * 16384;
    else if (t == 13) W = right_w + (size_t)i * 16384;
    else              W = ctr_w   + (size_t)i * 16384;
    uint32_t* img = g_wimg + (size_t)m * IMGW;

    for (int e = threadIdx.x; e < 64 * 128; e += 256) {
        int kp = e >> 7, n = e & 127;
        img[kp * S2 + n] = h2(__ldg(&W[(2 * kp) * 128 + n]), __ldg(&W[(2 * kp + 1) * 128 + n]));
    }
}

// ---------------- edge buckets (type, v-block) ----------------
__global__ void place_kernel(const int* __restrict__ pre_u, const int* __restrict__ pre_v,
                             const int* __restrict__ suc_u, const int* __restrict__ suc_v,
                             const int* __restrict__ left_u, const int* __restrict__ left_v,
                             const int* __restrict__ right_u, const int* __restrict__ right_v)
{
    int idx = blockIdx.x * 256 + threadIdx.x;
    int t, u, v;
    if (idx < 6 * EE)            { t = idx / EE; u = pre_u[idx]; v = pre_v[idx]; }
    else if (idx < 12 * EE)      { int j = idx - 6 * EE; t = idx / EE; u = suc_u[j]; v = suc_v[j]; }
    else if (idx < 12 * EE + EE2){ int j = idx - 12 * EE; t = 12; u = left_u[j]; v = left_v[j]; }
    else if (idx < TOTAL_E)      { int j = idx - 12 * EE - EE2; t = 13; u = right_u[j]; v = right_v[j]; }
    else return;
    int vb = v >> 7;
    int b = t * NBLK + vb;
    int cap  = (t < 12) ? CAP1 : CAP2;
    int base = (t < 12) ? b * CAP1 : (12 * NBLK * CAP1 + ((t - 12) * NBLK + vb) * CAP2);
    int pos = atomicAdd(&g_cnt[b], 1);
    if (pos < cap) g_edges[base + pos] = u | ((v & 127) << 18);
}

// ---------------- encoder stage 1 ----------------
__global__ __launch_bounds__(256) void enc1_kernel(
    const float* __restrict__ ctrs, const float* __restrict__ feats,
    const float* __restrict__ w_in1, const float* __restrict__ b_in1,
    const float* __restrict__ w_seg1, const float* __restrict__ b_seg1,
    float* __restrict__ h_in, float* __restrict__ h_seg)
{
    int idx = blockIdx.x * blockDim.x + threadIdx.x;
    int n = idx >> 5;
    if (n >= NN) return;
    int c = (idx & 31) * 4;

    float c0 = __ldg(&ctrs[2 * n]),  c1 = __ldg(&ctrs[2 * n + 1]);
    float f0 = __ldg(&feats[2 * n]), f1 = __ldg(&feats[2 * n + 1]);

    float4 wi0 = ld4(w_in1 + c), wi1 = ld4(w_in1 + DD + c), bi = ld4(b_in1 + c);
    float4 ws0 = ld4(w_seg1 + c), ws1 = ld4(w_seg1 + DD + c), bs = ld4(b_seg1 + c);

    float4 hi, hs;
    hi.x = fmaxf(c0 * wi0.x + c1 * wi1.x + bi.x, 0.f);
    hi.y = fmaxf(c0 * wi0.y + c1 * wi1.y + bi.y, 0.f);
    hi.z = fmaxf(c0 * wi0.z + c1 * wi1.z + bi.z, 0.f);
    hi.w = fmaxf(c0 * wi0.w + c1 * wi1.w + bi.w, 0.f);
    hs.x = fmaxf(f0 * ws0.x + f1 * ws1.x + bs.x, 0.f);
    hs.y = fmaxf(f0 * ws0.y + f1 * ws1.y + bs.y, 0.f);
    hs.z = fmaxf(f0 * ws0.z + f1 * ws1.z + bs.z, 0.f);
    hs.w = fmaxf(f0 * ws0.w + f1 * ws1.w + bs.w, 0.f);

    *(float4*)&h_in [n * DD + c] = hi;
    *(float4*)&h_seg[n * DD + c] = hs;
}

// ---------------- encoder GEMM pair (tf32 mma.sync, in-place) ----------------
__global__ __launch_bounds__(256, 2) void enc_gemm2_kernel(
    float* __restrict__ Ain, const float* __restrict__ Ba,
    float* __restrict__ Aseg, const float* __restrict__ Bb)
{
    extern __shared__ float sm[];
    float* Bs = sm;
    float* As = sm + 128 * ARB;

    int tid = threadIdx.x, lane = tid & 31, warp = tid >> 5;
    int gid = lane >> 2, tig = lane & 3;
    int wm = warp >> 1, wn = warp & 1;
    long rowBase = (long)blockIdx.x * 128;

    for (int p = 0; p < 2; p++) {
        float* A = p ? Aseg : Ain;
        const float* B = p ? Bb : Ba;

        for (int i = tid; i < 128 * 32; i += 256) {
            int r = i >> 5, c = (i & 31) * 4;
            float4 b = ld4(B + r * 128 + c);
            float* d = Bs + r * ARB + c;
            d[0] = tf32r(b.x); d[1] = tf32r(b.y); d[2] = tf32r(b.z); d[3] = tf32r(b.w);
        }

        float acc[2][8][4];
#pragma unroll
        for (int tm = 0; tm < 2; tm++)
#pragma unroll
            for (int nt = 0; nt < 8; nt++)
#pragma unroll
                for (int j = 0; j < 4; j++) acc[tm][nt][j] = 0.f;

        int lr = tid >> 1, lkh = (tid & 1) * 16;

        for (int kt = 0; kt < 128; kt += 32) {
            const float* ap = A + (rowBase + lr) * 128 + kt + lkh;
#pragma unroll
            for (int j = 0; j < 4; j++) {
                float4 a = ld4(ap + j * 4);
                int k0 = lkh + j * 4;
                As[(k0 + 0) * ARB + lr] = tf32r(a.x);
                As[(k0 + 1) * ARB + lr] = tf32r(a.y);
                As[(k0 + 2) * ARB + lr] = tf32r(a.z);
                As[(k0 + 3) * ARB + lr] = tf32r(a.w);
            }
            __syncthreads();

#pragma unroll
            for (int ks = 0; ks < 4; ks++) {
                uint32_t af[2][4];
#pragma unroll
                for (int tm = 0; tm < 2; tm++) {
                    int rr = wm * 32 + tm * 16 + gid;
                    const float* a0p = As + (ks * 8 + tig) * ARB + rr;
                    const float* a1p = As + (ks * 8 + tig + 4) * ARB + rr;
                    af[tm][0] = __float_as_uint(a0p[0]);
                    af[tm][1] = __float_as_uint(a0p[8]);
                    af[tm][2] = __float_as_uint(a1p[0]);
                    af[tm][3] = __float_as_uint(a1p[8]);
                }
#pragma unroll
                for (int nt = 0; nt < 8; nt++) {
                    int cc = wn * 64 + nt * 8 + gid;
                    uint32_t b0 = __float_as_uint(Bs[(kt + ks * 8 + tig) * ARB + cc]);
                    uint32_t b1 = __float_as_uint(Bs[(kt + ks * 8 + tig + 4) * ARB + cc]);
#pragma unroll
                    for (int tm = 0; tm < 2; tm++)
                        MMA_TF32(acc[tm][nt], af[tm][0], af[tm][1], af[tm][2], af[tm][3], b0, b1);
                }
            }
            __syncthreads();
        }

#pragma unroll
        for (int tm = 0; tm < 2; tm++) {
            long r0 = rowBase + wm * 32 + tm * 16 + gid;
#pragma unroll
            for (int nt = 0; nt < 8; nt++) {
                int cc = wn * 64 + nt * 8 + tig * 2;
                *(float2*)(A + r0 * 128 + cc)       = make_float2(acc[tm][nt][0], acc[tm][nt][1]);
                *(float2*)(A + (r0 + 8) * 128 + cc) = make_float2(acc[tm][nt][2], acc[tm][nt][3]);
            }
        }
        __syncthreads();
    }
}

// ---------------- GN helpers ----------------
__device__ __forceinline__ void gn_stats(float4 x, float& mean, float& kinv) {
    float s  = x.x + x.y + x.z + x.w;
    float sq = x.x * x.x + x.y * x.y + x.z * x.z + x.w * x.w;
    s  = wsum(s)  * (1.f / 128.f);
    sq = wsum(sq) * (1.f / 128.f);
    mean = s;
    float var = sq - s * s;
    kinv = rsqrtf(var + 1e-5f);
}

// enc2: feat = relu(gn(A) + gn(B)); zero A rows (tmp) for iter 0
__global__ __launch_bounds__(256) void enc2_kernel(
    float* __restrict__ A, const float* __restrict__ gA, const float* __restrict__ bA,
    const float* __restrict__ Bv, const float* __restrict__ gB, const float* __restrict__ bB,
    float* __restrict__ feat)
{
    int row = blockIdx.x * 8 + (threadIdx.x >> 5);
    if (row >= NN) return;
    int lane = threadIdx.x & 31;
    int c = lane * 4;
    float4 a = ld4(&A[(long)row * 128 + c]);
    float4 b = ld4(&Bv[(long)row * 128 + c]);
    float ma, ka, mb, kb;
    gn_stats(a, ma, ka);
    gn_stats(b, mb, kb);
    float4 ga = ld4(gA + c), ba = ld4(bA + c);
    float4 gb = ld4(gB + c), bb = ld4(bB + c);
    float4 o;
    o.x = fmaxf((a.x - ma) * ka * ga.x + ba.x + (b.x - mb) * kb * gb.x + bb.x, 0.f);
    o.y = fmaxf((a.y - ma) * ka * ga.y + ba.y + (b.y - mb) * kb * gb.y + bb.y, 0.f);
    o.z = fmaxf((a.z - ma) * ka * ga.z + ba.z + (b.z - mb) * kb * gb.z + bb.z, 0.f);
    o.w = fmaxf((a.w - ma) * ka * ga.w + ba.w + (b.w - mb) * kb * gb.w + bb.w, 0.f);
    *(float4*)&feat[(long)row * 128 + c] = o;
    *(float4*)&A   [(long)row * 128 + c] = make_float4(0.f, 0.f, 0.f, 0.f);
}

// ---------------- fused message-passing kernel (fp16 mma, cp.async B, smem edges) ----------------
__global__ __launch_bounds__(512) void fuse_kernel(
    const float* __restrict__ featIn, float* __restrict__ temp,
    const uint32_t* __restrict__ Wimg)
{
    extern __shared__ char smc[];
    uint32_t* As2 = (uint32_t*)(smc + F_A);
    uint32_t* Bs2 = (uint32_t*)(smc + F_B);       // 2 buffers of IMGW
    float*    Cs  = (float*)(smc + F_C);
    int*      EIX = (int*)(smc + F_E);

    uint32_t sb = smem_u32(smc);
    uint32_t bsA[2] = { sb + F_B, sb + F_B + IMGB };
    uint32_t eixA = sb + F_E;

    int tid = threadIdx.x, lane = tid & 31, warp = tid >> 5;
    int gid = lane >> 2, tig = lane & 3;
    int wm = warp >> 2, wn = warp & 3;            // 4x4 warp grid, tile 32x32
    int bid = blockIdx.x;
    long rowBase = (long)bid * 128;

    // --- async group 0: edge indices (3200 words) + B(0) image ---
    for (int ch = tid; ch < 800; ch += 512) {
        int w = ch * 4;
        int srcw;
        if (w < 3072) {
            int t = w >> 8, off = w & 255;
            srcw = (t * NBLK + bid) * CAP1 + off;
        } else {
            int j = w - 3072;
            int t = j >> 6, off = j & 63;        // t 0/1 -> left/right
            srcw = 12 * NBLK * CAP1 + (t * NBLK + bid) * CAP2 + off;
        }
        cpa16(eixA + w * 4, g_edges + srcw);
    }
    for (int ch = tid; ch < IMGB / 16; ch += 512)
        cpa16(bsA[0] + ch * 16, (const char*)Wimg + ch * 16);
    cp_commit();

    // --- load A tile (fp16 pairs) ---
    {
        int r = tid >> 2, q = tid & 3;
        const float* ap = featIn + (rowBase + r) * 128 + q * 32;
#pragma unroll
        for (int j = 0; j < 8; j++) {
            float4 a = ld4(ap + j * 4);
            int kp = q * 16 + j * 2;
            As2[(kp + 0) * S2 + r] = h2(a.x, a.y);
            As2[(kp + 1) * S2 + r] = h2(a.z, a.w);
        }
    }

    for (int t = 0; t < 15; t++) {
        // issue B(t+1), then wait for B(t) (and at t=0 also edges/As sync)
        if (t < 14) {
            const char* src = (const char*)(Wimg + (size_t)(t + 1) * IMGW);
            uint32_t dst = bsA[(t + 1) & 1];
            for (int ch = tid; ch < IMGB / 16; ch += 512)
                cpa16(dst + ch * 16, src + ch * 16);
            cp_commit();
            cp_wait<1>();
        } else {
            cp_wait<0>();
        }
        __syncthreads();   // B(t)+edges visible; scatter(t-1) done with Cs; As2 ready (t=0)

        const uint32_t* Bb = Bs2 + ((t & 1) ? IMGW : 0);

        float acc[2][4][4];
#pragma unroll
        for (int tm = 0; tm < 2; tm++)
#pragma unroll
            for (int nt = 0; nt < 4; nt++)
#pragma unroll
                for (int j = 0; j < 4; j++) acc[tm][nt][j] = 0.f;

#pragma unroll
        for (int ks = 0; ks < 8; ks++) {
            int kk = ks * 8;
            uint32_t af[2][4];
#pragma unroll
            for (int tm = 0; tm < 2; tm++) {
                int rr = wm * 32 + tm * 16 + gid;
                const uint32_t* a0p = As2 + (kk + tig) * S2 + rr;
                const uint32_t* a1p = As2 + (kk + tig + 4) * S2 + rr;
                af[tm][0] = a0p[0];
                af[tm][1] = a0p[8];
                af[tm][2] = a1p[0];
                af[tm][3] = a1p[8];
            }
#pragma unroll
            for (int nt = 0; nt < 4; nt++) {
                int cc = wn * 32 + nt * 8 + gid;
                uint32_t b0 = Bb[(kk + tig) * S2 + cc];
                uint32_t b1 = Bb[(kk + tig + 4) * S2 + cc];
#pragma unroll
                for (int tm = 0; tm < 2; tm++)
                    MMA_F16(acc[tm][nt], af[tm][0], af[tm][1], af[tm][2], af[tm][3], b0, b1);
            }
        }

        // stage C (warp-owned rows)
#pragma unroll
        for (int tm = 0; tm < 2; tm++) {
            int r0 = wm * 32 + tm * 16 + gid;
#pragma unroll
            for (int nt = 0; nt < 4; nt++) {
                int cc = wn * 32 + nt * 8 + tig * 2;
                *(float2*)(Cs + r0 * CSTR + cc)       = make_float2(acc[tm][nt][0], acc[tm][nt][1]);
                *(float2*)(Cs + (r0 + 8) * CSTR + cc) = make_float2(acc[tm][nt][2], acc[tm][nt][3]);
            }
        }
        __syncthreads();

        // scatter from Cs using smem edge indices
        if (t < 14) {
            int len = g_cnt[t * NBLK + bid];
            int cap = (t < 12) ? CAP1 : CAP2;
            if (len > cap) len = cap;
            int ebase = (t < 12) ? t * CAP1 : 3072 + (t - 12) * CAP2;
            for (int e = warp; e < len; e += 16) {
                int pk = EIX[ebase + e];
                int u  = pk & 0x3FFFF;
                int vl = pk >> 18;
                float4 y = *(float4*)(Cs + vl * CSTR + lane * 4);
                redv4(temp + (long)u * 128 + lane * 4, y);
            }
        } else {
            for (int r = warp; r < 128; r += 16) {
                float4 y = *(float4*)(Cs + r * CSTR + lane * 4);
                redv4(temp + (rowBase + r) * 128 + lane * 4, y);
            }
        }
        // next iteration's first sync protects Cs before restaging
    }
}

// ---------------- post: fp16 mma; feat = relu(gn2(relu(gn1(tmp)) @ ctr2_w) + feat_old) ----------------
__global__ __launch_bounds__(256, 2) void post_kernel(
    float* __restrict__ tmp, float* __restrict__ feat,
    const float* __restrict__ Bw,
    const float* __restrict__ ng, const float* __restrict__ nb,
    const float* __restrict__ g2, const float* __restrict__ b2,
    float* __restrict__ dout, int zero_tmp)
{
    extern __shared__ char smc[];
    uint32_t* As2 = (uint32_t*)(smc);
    uint32_t* Bs2 = (uint32_t*)(smc + 34816);
    float*    Cs  = (float*)(smc);                // union after GEMM

    int tid = threadIdx.x, lane = tid & 31, warp = tid >> 5;
    int gid = lane >> 2, tig = lane & 3;
    int wm = warp >> 1, wn = warp & 1;
    long rowBase = (long)blockIdx.x * 128;

    {
        int r = tid >> 1;
        int h = (tid & 1) * 64;
        float* xp = tmp + (rowBase + r) * 128 + h;
        float s = 0.f, sq = 0.f;
        float4 av[16];
#pragma unroll
        for (int j = 0; j < 16; j++) {
            av[j] = ld4(xp + j * 4);
            s  += av[j].x + av[j].y + av[j].z + av[j].w;
            sq += av[j].x * av[j].x + av[j].y * av[j].y + av[j].z * av[j].z + av[j].w * av[j].w;
        }
        s  += __shfl_xor_sync(0xffffffffu, s, 1);
        sq += __shfl_xor_sync(0xffffffffu, sq, 1);
        float mean = s * (1.f / 128.f);
        float kinv = rsqrtf(sq * (1.f / 128.f) - mean * mean + 1e-5f);
        int h2base = h >> 1;
#pragma unroll
        for (int j = 0; j < 16; j++) {
            int k = h + j * 4;
            float4 gg = ld4(ng + k), bb = ld4(nb + k);
            float ox = fmaxf((av[j].x - mean) * kinv * gg.x + bb.x, 0.f);
            float oy = fmaxf((av[j].y - mean) * kinv * gg.y + bb.y, 0.f);
            float oz = fmaxf((av[j].z - mean) * kinv * gg.z + bb.z, 0.f);
            float ow = fmaxf((av[j].w - mean) * kinv * gg.w + bb.w, 0.f);
            As2[(h2base + j * 2 + 0) * S2 + r] = h2(ox, oy);
            As2[(h2base + j * 2 + 1) * S2 + r] = h2(oz, ow);
        }
        if (zero_tmp) {
            float4 z = make_float4(0.f, 0.f, 0.f, 0.f);
#pragma unroll
            for (int j = 0; j < 16; j++) *(float4*)(xp + j * 4) = z;
        }
    }

#pragma unroll
    for (int j = 0; j < 8; j++) {
        int idx = tid + j * 256;
        int kp = idx >> 5, cg = (idx & 31) * 4;
        float4 lo = ld4(Bw + (2 * kp) * 128 + cg);
        float4 hi = ld4(Bw + (2 * kp + 1) * 128 + cg);
        uint4 v;
        v.x = h2(lo.x, hi.x);
        v.y = h2(lo.y, hi.y);
        v.z = h2(lo.z, hi.z);
        v.w = h2(lo.w, hi.w);
        *(uint4*)(Bs2 + kp * S2 + cg) = v;
    }
    __syncthreads();

    float acc[2][8][4];
#pragma unroll
    for (int tm = 0; tm < 2; tm++)
#pragma unroll
        for (int nt = 0; nt < 8; nt++)
#pragma unroll
            for (int j = 0; j < 4; j++) acc[tm][nt][j] = 0.f;

#pragma unroll
    for (int ks = 0; ks < 8; ks++) {
        int kk = ks * 8;
        uint32_t af[2][4];
#pragma unroll
        for (int tm = 0; tm < 2; tm++) {
            int rr = wm * 32 + tm * 16 + gid;
            const uint32_t* a0p = As2 + (kk + tig) * S2 + rr;
            const uint32_t* a1p = As2 + (kk + tig + 4) * S2 + rr;
            af[tm][0] = a0p[0];
            af[tm][1] = a0p[8];
            af[tm][2] = a1p[0];
            af[tm][3] = a1p[8];
        }
#pragma unroll
        for (int nt = 0; nt < 8; nt++) {
            int cc = wn * 64 + nt * 8 + gid;
            uint32_t b0 = Bs2[(kk + tig) * S2 + cc];
            uint32_t b1 = Bs2[(kk + tig + 4) * S2 + cc];
#pragma unroll
            for (int tm = 0; tm < 2; tm++)
                MMA_F16(acc[tm][nt], af[tm][0], af[tm][1], af[tm][2], af[tm][3], b0, b1);
        }
    }
    __syncthreads();

#pragma unroll
    for (int tm = 0; tm < 2; tm++) {
        int r0 = wm * 32 + tm * 16 + gid;
#pragma unroll
        for (int nt = 0; nt < 8; nt++) {
            int cc = wn * 64 + nt * 8 + tig * 2;
            *(float2*)(Cs + r0 * CSTR + cc)       = make_float2(acc[tm][nt][0], acc[tm][nt][1]);
            *(float2*)(Cs + (r0 + 8) * CSTR + cc) = make_float2(acc[tm][nt][2], acc[tm][nt][3]);
        }
    }
    __syncthreads();

    for (int r = warp; r < 128; r += 8) {
        int c = lane * 4;
        float4 x = *(float4*)(Cs + r * CSTR + c);
        float m, k;
        gn_stats(x, m, k);
        float4 gg = ld4(g2 + c), bb = ld4(b2 + c);
        long grow = rowBase + r;
        float4 old = ld4(feat + grow * 128 + c);
        float4 o;
        o.x = fmaxf((x.x - m) * k * gg.x + bb.x + old.x, 0.f);
        o.y = fmaxf((x.y - m) * k * gg.y + bb.y + old.y, 0.f);
        o.z = fmaxf((x.z - m) * k * gg.z + bb.z + old.z, 0.f);
        o.w = fmaxf((x.w - m) * k * gg.w + bb.w + old.w, 0.f);
        *(float4*)(feat + grow * 128 + c) = o;
        if (dout && grow < NN) *(float4*)(dout + grow * 128 + c) = o;
    }
}

// ---------------- host launcher ----------------
extern "C" void kernel_launch(void* const* d_in, const int* in_sizes, int n_in,
                              void* d_out, int out_size)
{
    const float* ctrs   = (const float*)d_in[0];
    const float* feats  = (const float*)d_in[1];
    const float* w_in1  = (const float*)d_in[2];
    const float* b_in1  = (const float*)d_in[3];
    const float* w_in2  = (const float*)d_in[4];
    const float* g_in   = (const float*)d_in[5];
    const float* be_in  = (const float*)d_in[6];
    const float* w_seg1 = (const float*)d_in[7];
    const float* b_seg1 = (const float*)d_in[8];
    const float* w_seg2 = (const float*)d_in[9];
    const float* g_seg  = (const float*)d_in[10];
    const float* be_seg = (const float*)d_in[11];
    const float* ctr_w  = (const float*)d_in[12];
    const float* pre_w  = (const float*)d_in[13];
    const float* suc_w  = (const float*)d_in[14];
    const float* left_w = (const float*)d_in[15];
    const float* right_w= (const float*)d_in[16];
    const float* norm_g = (const float*)d_in[17];
    const float* norm_b = (const float*)d_in[18];
    const float* ctr2_w = (const float*)d_in[19];
    const float* ctr2_g = (const float*)d_in[20];
    const float* ctr2_b = (const float*)d_in[21];
    const int* pre_u  = (const int*)d_in[22];
    const int* pre_v  = (const int*)d_in[23];
    const int* suc_u  = (const int*)d_in[24];
    const int* suc_v  = (const int*)d_in[25];
    const int* left_u = (const int*)d_in[26];
    const int* left_v = (const int*)d_in[27];
    const int* right_u= (const int*)d_in[28];
    const int* right_v= (const int*)d_in[29];

    float *feat, *tmp, *y;
    int *cnt;
    uint32_t *wimg;
    cudaGetSymbolAddress((void**)&feat, g_feat);
    cudaGetSymbolAddress((void**)&tmp,  g_tmp);
    cudaGetSymbolAddress((void**)&y,    g_y);
    cudaGetSymbolAddress((void**)&cnt,  g_cnt);
    cudaGetSymbolAddress((void**)&wimg, g_wimg);

    const int MAT = 128 * 128;
    const int SMEM_GEMM = 160 * ARB * 4;   // 87040 (encoder tf32 kernel)
    const int EB = (TOTAL_E + 255) / 256;

    static bool attr_set = false;
    if (!attr_set) {
        cudaFuncSetAttribute(enc_gemm2_kernel, cudaFuncAttributeMaxDynamicSharedMemorySize, SMEM_GEMM);
        cudaFuncSetAttribute(post_kernel,      cudaFuncAttributeMaxDynamicSharedMemorySize, SMEM_POST);
        cudaFuncSetAttribute(fuse_kernel,      cudaFuncAttributeMaxDynamicSharedMemorySize, SMEM_FUSE3);
        attr_set = true;
    }

    cudaMemsetAsync(cnt, 0, NBUCK * sizeof(int));
    place_kernel<<<EB, 256>>>(pre_u, pre_v, suc_u, suc_v, left_u, left_v, right_u, right_v);
    prep_kernel<<<60, 256>>>(pre_w, suc_w, left_w, right_w, ctr_w);

    enc1_kernel<<<(NN * 32) / 256, 256>>>(ctrs, feats, w_in1, b_in1, w_seg1, b_seg1, tmp, y);
    enc_gemm2_kernel<<<NBLK, 256, SMEM_GEMM>>>(tmp, w_in2, y, w_seg2);
    enc2_kernel<<<NN / 8, 256>>>(tmp, g_in, be_in, y, g_seg, be_seg, feat);

    for (int i = 0; i < LL; i++) {
        fuse_kernel<<<NBLK, 512, SMEM_FUSE3>>>(feat, tmp, wimg + (size_t)i * 15 * IMGW);
        post_kernel<<<NBLK, 256, SMEM_POST>>>(
            tmp, feat, ctr2_w + (size_t)i * MAT,
            norm_g + i * 128, norm_b + i * 128,
            ctr2_g + i * 128, ctr2_b + i * 128,
            (i == LL - 1) ? (float*)d_out : nullptr,
            (i < LL - 1) ? 1 : 0);
    }
}

// round 10
// speedup vs baseline: 1.6550x; 1.0557x over previous
#include <cuda_runtime.h>
#include <cuda_fp16.h>
#include <cstdint>

#define NN 200000
#define NPAD 200064     // 1563 * 128
#define DD 128
#define EE 200000
#define EE2 20000
#define SS 6
#define LL 4
#define NBLK 1563
#define S2  136         // fp16 half2 smem stride (uint32 units) for scalar-LDS kernels
#define RSW 68          // row stride in words for ldmatrix layout (136 halves)
#define RSB 272         // row stride bytes
#define CSTR 132        // C staging stride (fp32 words): 528B rows, 16B aligned
#define NTYPE 14
#define NBUCK (NTYPE * NBLK)
#define TOTAL_E (12 * EE + 2 * EE2)
#define CAP1 256
#define CAP2 64
#define EDGESZ (12 * NBLK * CAP1 + 2 * NBLK * CAP2)

#define IMGW (128 * RSW)        // uint32 words per prepped B image (8704)
#define IMGB (IMGW * 4)         // 34816 bytes

// fuse smem layout (bytes)
#define F_A   0                         // A tile (ldmatrix layout): 34816
#define F_B   34816                     // B x2: 69632
#define F_C   (34816 + 69632)           // Cs: 67584
#define F_E   (34816 + 69632 + 67584)   // EIX: 12800
#define SMEM_FUSE3 (34816 + 69632 + 67584 + 12800)   // 184832
#define SMEM_POST 69632
#define SMEM_ENC  69632

// ---------------- device scratch ----------------
__device__ float g_feat[NPAD * DD];
__device__ float g_y   [NPAD * DD];
__device__ float g_tmp [NPAD * DD];
__device__ int   g_cnt [NBUCK];
__device__ int   g_edges[EDGESZ];
__device__ uint32_t g_wimg[60 * IMGW];   // prepped fp16 B^T images, [n][k] row-major

__device__ __forceinline__ float4 ld4(const float* p) { return *(const float4*)(p); }

// pack (lo=first-k, hi=second-k) into b32 f16x2 (lower half = lo)
__device__ __forceinline__ uint32_t h2(float lo, float hi) {
    uint32_t r;
    asm("cvt.rn.f16x2.f32 %0, %1, %2;" : "=r"(r) : "f"(hi), "f"(lo));
    return r;
}

__device__ __forceinline__ float wsum(float s) {
#pragma unroll
    for (int o = 16; o; o >>= 1) s += __shfl_xor_sync(0xffffffffu, s, o);
    return s;
}

__device__ __forceinline__ void redv4(float* p, float4 y) {
    asm volatile("red.global.add.v4.f32 [%0], {%1,%2,%3,%4};"
                 :: "l"(p), "f"(y.x), "f"(y.y), "f"(y.z), "f"(y.w) : "memory");
}

__device__ __forceinline__ uint32_t smem_u32(const void* p) {
    uint32_t a;
    asm("{ .reg .u64 t; cvta.to.shared.u64 t, %1; cvt.u32.u64 %0, t; }" : "=r"(a) : "l"(p));
    return a;
}

__device__ __forceinline__ void cpa16(uint32_t dst, const void* src) {
    asm volatile("cp.async.cg.shared.global [%0], [%1], 16;" :: "r"(dst), "l"(src));
}
__device__ __forceinline__ void cp_commit() {
    asm volatile("cp.async.commit_group;" ::: "memory");
}
template<int N>
__device__ __forceinline__ void cp_wait() {
    asm volatile("cp.async.wait_group %0;" :: "n"(N) : "memory");
}

#define LDSM_X4(r0, r1, r2, r3, addr) \
    asm volatile("ldmatrix.sync.aligned.m8n8.x4.shared.b16 {%0,%1,%2,%3}, [%4];" \
                 : "=r"(r0), "=r"(r1), "=r"(r2), "=r"(r3) : "r"(addr))

#define MMA_F16(acc, a0, a1, a2, a3, b0, b1) \
    asm volatile( \
        "mma.sync.aligned.m16n8k16.row.col.f32.f16.f16.f32 " \
        "{%0,%1,%2,%3}, {%4,%5,%6,%7}, {%8,%9}, {%0,%1,%2,%3};\n" \
        : "+f"((acc)[0]), "+f"((acc)[1]), "+f"((acc)[2]), "+f"((acc)[3]) \
        : "r"(a0), "r"(a1), "r"(a2), "r"(a3), "r"(b0), "r"(b1))

// ---------------- weight prep: fp32 W[k][n] -> fp16 image W^T [n][k], stride RSW ----------------
__global__ __launch_bounds__(256) void prep_kernel(
    const float* __restrict__ pre_w, const float* __restrict__ suc_w,
    const float* __restrict__ left_w, const float* __restrict__ right_w,
    const float* __restrict__ ctr_w)
{
    int m = blockIdx.x;              // 0..59
    int i = m / 15, t = m % 15;
    const float* W;
    if (t < 6)        W = pre_w  + (size_t)(i * 6 + t) * 16384;
    else if (t < 12)  W = suc_w  + (size_t)(i * 6 + (t - 6)) * 16384;
    else if (t == 12) W = left_w  + (size_t)i * 16384;
    else if (t == 13) W = right_w + (size_t)i * 16384;
    else              W = ctr_w   + (size_t)i * 16384;
    uint32_t* img = g_wimg + (size_t)m * IMGW;

    for (int e = threadIdx.x; e < 128 * 64; e += 256) {
        int n = e >> 6, kp = e & 63;
        img[n * RSW + kp] = h2(__ldg(&W[(2 * kp) * 128 + n]), __ldg(&W[(2 * kp + 1) * 128 + n]));
    }
}

// ---------------- edge buckets (type, v-block) ----------------
__global__ void place_kernel(const int* __restrict__ pre_u, const int* __restrict__ pre_v,
                             const int* __restrict__ suc_u, const int* __restrict__ suc_v,
                             const int* __restrict__ left_u, const int* __restrict__ left_v,
                             const int* __restrict__ right_u, const int* __restrict__ right_v)
{
    int idx = blockIdx.x * 256 + threadIdx.x;
    int t, u, v;
    if (idx < 6 * EE)            { t = idx / EE; u = pre_u[idx]; v = pre_v[idx]; }
    else if (idx < 12 * EE)      { int j = idx - 6 * EE; t = idx / EE; u = suc_u[j]; v = suc_v[j]; }
    else if (idx < 12 * EE + EE2){ int j = idx - 12 * EE; t = 12; u = left_u[j]; v = left_v[j]; }
    else if (idx < TOTAL_E)      { int j = idx - 12 * EE - EE2; t = 13; u = right_u[j]; v = right_v[j]; }
    else return;
    int vb = v >> 7;
    int b = t * NBLK + vb;
    int cap  = (t < 12) ? CAP1 : CAP2;
    int base = (t < 12) ? b * CAP1 : (12 * NBLK * CAP1 + ((t - 12) * NBLK + vb) * CAP2);
    int pos = atomicAdd(&g_cnt[b], 1);
    if (pos < cap) g_edges[base + pos] = u | ((v & 127) << 18);
}

// ---------------- encoder stage 1 ----------------
__global__ __launch_bounds__(256) void enc1_kernel(
    const float* __restrict__ ctrs, const float* __restrict__ feats,
    const float* __restrict__ w_in1, const float* __restrict__ b_in1,
    const float* __restrict__ w_seg1, const float* __restrict__ b_seg1,
    float* __restrict__ h_in, float* __restrict__ h_seg)
{
    int idx = blockIdx.x * blockDim.x + threadIdx.x;
    int n = idx >> 5;
    if (n >= NN) return;
    int c = (idx & 31) * 4;

    float c0 = __ldg(&ctrs[2 * n]),  c1 = __ldg(&ctrs[2 * n + 1]);
    float f0 = __ldg(&feats[2 * n]), f1 = __ldg(&feats[2 * n + 1]);

    float4 wi0 = ld4(w_in1 + c), wi1 = ld4(w_in1 + DD + c), bi = ld4(b_in1 + c);
    float4 ws0 = ld4(w_seg1 + c), ws1 = ld4(w_seg1 + DD + c), bs = ld4(b_seg1 + c);

    float4 hi, hs;
    hi.x = fmaxf(c0 * wi0.x + c1 * wi1.x + bi.x, 0.f);
    hi.y = fmaxf(c0 * wi0.y + c1 * wi1.y + bi.y, 0.f);
    hi.z = fmaxf(c0 * wi0.z + c1 * wi1.z + bi.z, 0.f);
    hi.w = fmaxf(c0 * wi0.w + c1 * wi1.w + bi.w, 0.f);
    hs.x = fmaxf(f0 * ws0.x + f1 * ws1.x + bs.x, 0.f);
    hs.y = fmaxf(f0 * ws0.y + f1 * ws1.y + bs.y, 0.f);
    hs.z = fmaxf(f0 * ws0.z + f1 * ws1.z + bs.z, 0.f);
    hs.w = fmaxf(f0 * ws0.w + f1 * ws1.w + bs.w, 0.f);

    *(float4*)&h_in [n * DD + c] = hi;
    *(float4*)&h_seg[n * DD + c] = hs;
}

// ---------------- encoder GEMM pair (fp16 mma, in-place) ----------------
__global__ __launch_bounds__(256, 2) void enc_gemm2_kernel(
    float* __restrict__ Ain, const float* __restrict__ Ba,
    float* __restrict__ Aseg, const float* __restrict__ Bb)
{
    extern __shared__ char smc[];
    uint32_t* As2 = (uint32_t*)(smc);             // [64 kpair][S2]
    uint32_t* Bs2 = (uint32_t*)(smc + 34816);

    int tid = threadIdx.x, lane = tid & 31, warp = tid >> 5;
    int gid = lane >> 2, tig = lane & 3;
    int wm = warp >> 1, wn = warp & 1;            // 4x2 grid, warp tile 32x64
    long rowBase = (long)blockIdx.x * 128;

    for (int p = 0; p < 2; p++) {
        float* A = p ? Aseg : Ain;
        const float* B = p ? Bb : Ba;

        // A -> fp16 pairs
        {
            int r = tid >> 1;
            int h = (tid & 1) * 64;
            const float* ap = A + (rowBase + r) * 128 + h;
            int hb = h >> 1;
#pragma unroll
            for (int j = 0; j < 16; j++) {
                float4 a = ld4(ap + j * 4);
                As2[(hb + j * 2 + 0) * S2 + r] = h2(a.x, a.y);
                As2[(hb + j * 2 + 1) * S2 + r] = h2(a.z, a.w);
            }
        }
        // B -> fp16 pairs
#pragma unroll
        for (int j = 0; j < 8; j++) {
            int idx = tid + j * 256;
            int kp = idx >> 5, cg = (idx & 31) * 4;
            float4 lo = ld4(B + (2 * kp) * 128 + cg);
            float4 hi = ld4(B + (2 * kp + 1) * 128 + cg);
            uint4 v;
            v.x = h2(lo.x, hi.x);
            v.y = h2(lo.y, hi.y);
            v.z = h2(lo.z, hi.z);
            v.w = h2(lo.w, hi.w);
            *(uint4*)(Bs2 + kp * S2 + cg) = v;
        }
        __syncthreads();

        float acc[2][8][4];
#pragma unroll
        for (int tm = 0; tm < 2; tm++)
#pragma unroll
            for (int nt = 0; nt < 8; nt++)
#pragma unroll
                for (int j = 0; j < 4; j++) acc[tm][nt][j] = 0.f;

#pragma unroll
        for (int ks = 0; ks < 8; ks++) {
            int kk = ks * 8;
            uint32_t af[2][4];
#pragma unroll
            for (int tm = 0; tm < 2; tm++) {
                int rr = wm * 32 + tm * 16 + gid;
                const uint32_t* a0p = As2 + (kk + tig) * S2 + rr;
                const uint32_t* a1p = As2 + (kk + tig + 4) * S2 + rr;
                af[tm][0] = a0p[0];
                af[tm][1] = a0p[8];
                af[tm][2] = a1p[0];
                af[tm][3] = a1p[8];
            }
#pragma unroll
            for (int nt = 0; nt < 8; nt++) {
                int cc = wn * 64 + nt * 8 + gid;
                uint32_t b0 = Bs2[(kk + tig) * S2 + cc];
                uint32_t b1 = Bs2[(kk + tig + 4) * S2 + cc];
#pragma unroll
                for (int tm = 0; tm < 2; tm++)
                    MMA_F16(acc[tm][nt], af[tm][0], af[tm][1], af[tm][2], af[tm][3], b0, b1);
            }
        }
        __syncthreads();

#pragma unroll
        for (int tm = 0; tm < 2; tm++) {
            long r0 = rowBase + wm * 32 + tm * 16 + gid;
#pragma unroll
            for (int nt = 0; nt < 8; nt++) {
                int cc = wn * 64 + nt * 8 + tig * 2;
                *(float2*)(A + r0 * 128 + cc)       = make_float2(acc[tm][nt][0], acc[tm][nt][1]);
                *(float2*)(A + (r0 + 8) * 128 + cc) = make_float2(acc[tm][nt][2], acc[tm][nt][3]);
            }
        }
        __syncthreads();
    }
}

// ---------------- GN helpers ----------------
__device__ __forceinline__ void gn_stats(float4 x, float& mean, float& kinv) {
    float s  = x.x + x.y + x.z + x.w;
    float sq = x.x * x.x + x.y * x.y + x.z * x.z + x.w * x.w;
    s  = wsum(s)  * (1.f / 128.f);
    sq = wsum(sq) * (1.f / 128.f);
    mean = s;
    float var = sq - s * s;
    kinv = rsqrtf(var + 1e-5f);
}

// enc2: feat = relu(gn(A) + gn(B)); zero A rows (tmp) for iter 0
__global__ __launch_bounds__(256) void enc2_kernel(
    float* __restrict__ A, const float* __restrict__ gA, const float* __restrict__ bA,
    const float* __restrict__ Bv, const float* __restrict__ gB, const float* __restrict__ bB,
    float* __restrict__ feat)
{
    int row = blockIdx.x * 8 + (threadIdx.x >> 5);
    if (row >= NN) return;
    int lane = threadIdx.x & 31;
    int c = lane * 4;
    float4 a = ld4(&A[(long)row * 128 + c]);
    float4 b = ld4(&Bv[(long)row * 128 + c]);
    float ma, ka, mb, kb;
    gn_stats(a, ma, ka);
    gn_stats(b, mb, kb);
    float4 ga = ld4(gA + c), ba = ld4(bA + c);
    float4 gb = ld4(gB + c), bb = ld4(bB + c);
    float4 o;
    o.x = fmaxf((a.x - ma) * ka * ga.x + ba.x + (b.x - mb) * kb * gb.x + bb.x, 0.f);
    o.y = fmaxf((a.y - ma) * ka * ga.y + ba.y + (b.y - mb) * kb * gb.y + bb.y, 0.f);
    o.z = fmaxf((a.z - ma) * ka * ga.z + ba.z + (b.z - mb) * kb * gb.z + bb.z, 0.f);
    o.w = fmaxf((a.w - ma) * ka * ga.w + ba.w + (b.w - mb) * kb * gb.w + bb.w, 0.f);
    *(float4*)&feat[(long)row * 128 + c] = o;
    *(float4*)&A   [(long)row * 128 + c] = make_float4(0.f, 0.f, 0.f, 0.f);
}

// ---------------- fused message-passing kernel (fp16 mma + ldmatrix) ----------------
__global__ __launch_bounds__(512) void fuse_kernel(
    const float* __restrict__ featIn, float* __restrict__ temp,
    const uint32_t* __restrict__ Wimg)
{
    extern __shared__ char smc[];
    float* Cs  = (float*)(smc + F_C);
    int*   EIX = (int*)(smc + F_E);

    uint32_t sb = smem_u32(smc);
    uint32_t eixA = sb + F_E;

    int tid = threadIdx.x, lane = tid & 31, warp = tid >> 5;
    int gid = lane >> 2, tig = lane & 3;
    int wm = warp >> 2, wn = warp & 3;            // 4x4 warp grid, tile 32x32
    int bid = blockIdx.x;
    long rowBase = (long)bid * 128;

    // --- async group 0: edge indices (3200 words) + B(0) image ---
    for (int ch = tid; ch < 800; ch += 512) {
        int w = ch * 4;
        int srcw;
        if (w < 3072) {
            int t = w >> 8, off = w & 255;
            srcw = (t * NBLK + bid) * CAP1 + off;
        } else {
            int j = w - 3072;
            int t = j >> 6, off = j & 63;
            srcw = 12 * NBLK * CAP1 + (t * NBLK + bid) * CAP2 + off;
        }
        cpa16(eixA + w * 4, g_edges + srcw);
    }
    for (int ch = tid; ch < IMGB / 16; ch += 512)
        cpa16(sb + F_B + ch * 16, (const char*)Wimg + ch * 16);
    cp_commit();

    // --- load A tile: row-major fp16 [row][k], stride RSW words ---
    {
        int r = tid >> 2, q = tid & 3;
        const float* ap = featIn + (rowBase + r) * 128 + q * 32;
        char* dst = smc + F_A + r * RSB + q * 64;
#pragma unroll
        for (int j = 0; j < 8; j++) {
            float4 a = ld4(ap + j * 4);
            uint2 v;
            v.x = h2(a.x, a.y);
            v.y = h2(a.z, a.w);
            *(uint2*)(dst + j * 8) = v;
        }
    }

    // per-warp ldmatrix base addresses
    uint32_t aBase = sb + F_A
        + (uint32_t)(wm * 32 + (lane & 7) + ((lane & 8) ? 8 : 0)) * RSB
        + ((lane & 16) ? 16 : 0);
    uint32_t bBase = sb + F_B
        + (uint32_t)(wn * 32 + (lane & 7) + ((lane & 16) ? 8 : 0)) * RSB
        + ((lane & 8) ? 16 : 0);

    for (int t = 0; t < 15; t++) {
        if (t < 14) {
            const char* src = (const char*)(Wimg + (size_t)(t + 1) * IMGW);
            uint32_t dst = sb + F_B + ((t + 1) & 1) * IMGB;
            for (int ch = tid; ch < IMGB / 16; ch += 512)
                cpa16(dst + ch * 16, src + ch * 16);
            cp_commit();
            cp_wait<1>();
        } else {
            cp_wait<0>();
        }
        __syncthreads();   // B(t)+edges visible; scatter(t-1) done with Cs; A ready (t=0)

        uint32_t bOff = (uint32_t)(t & 1) * IMGB;

        float acc[2][4][4];
#pragma unroll
        for (int tm = 0; tm < 2; tm++)
#pragma unroll
            for (int nt = 0; nt < 4; nt++)
#pragma unroll
                for (int j = 0; j < 4; j++) acc[tm][nt][j] = 0.f;

#pragma unroll
        for (int ks = 0; ks < 8; ks++) {
            uint32_t af0[4], af1[4], bf0[4], bf1[4];
            LDSM_X4(af0[0], af0[1], af0[2], af0[3], aBase + ks * 32);
            LDSM_X4(af1[0], af1[1], af1[2], af1[3], aBase + 16 * RSB + ks * 32);
            LDSM_X4(bf0[0], bf0[1], bf0[2], bf0[3], bBase + bOff + ks * 32);
            LDSM_X4(bf1[0], bf1[1], bf1[2], bf1[3], bBase + bOff + 16 * RSB + ks * 32);

            MMA_F16(acc[0][0], af0[0], af0[1], af0[2], af0[3], bf0[0], bf0[1]);
            MMA_F16(acc[1][0], af1[0], af1[1], af1[2], af1[3], bf0[0], bf0[1]);
            MMA_F16(acc[0][1], af0[0], af0[1], af0[2], af0[3], bf0[2], bf0[3]);
            MMA_F16(acc[1][1], af1[0], af1[1], af1[2], af1[3], bf0[2], bf0[3]);
            MMA_F16(acc[0][2], af0[0], af0[1], af0[2], af0[3], bf1[0], bf1[1]);
            MMA_F16(acc[1][2], af1[0], af1[1], af1[2], af1[3], bf1[0], bf1[1]);
            MMA_F16(acc[0][3], af0[0], af0[1], af0[2], af0[3], bf1[2], bf1[3]);
            MMA_F16(acc[1][3], af1[0], af1[1], af1[2], af1[3], bf1[2], bf1[3]);
        }

        // stage C (warp-owned rows)
#pragma unroll
        for (int tm = 0; tm < 2; tm++) {
            int r0 = wm * 32 + tm * 16 + gid;
#pragma unroll
            for (int nt = 0; nt < 4; nt++) {
                int cc = wn * 32 + nt * 8 + tig * 2;
                *(float2*)(Cs + r0 * CSTR + cc)       = make_float2(acc[tm][nt][0], acc[tm][nt][1]);
                *(float2*)(Cs + (r0 + 8) * CSTR + cc) = make_float2(acc[tm][nt][2], acc[tm][nt][3]);
            }
        }
        __syncthreads();

        // scatter from Cs using smem edge indices
        if (t < 14) {
            int len = g_cnt[t * NBLK + bid];
            int cap = (t < 12) ? CAP1 : CAP2;
            if (len > cap) len = cap;
            int ebase = (t < 12) ? t * CAP1 : 3072 + (t - 12) * CAP2;
            for (int e = warp; e < len; e += 16) {
                int pk = EIX[ebase + e];
                int u  = pk & 0x3FFFF;
                int vl = pk >> 18;
                float4 y = *(float4*)(Cs + vl * CSTR + lane * 4);
                redv4(temp + (long)u * 128 + lane * 4, y);
            }
        } else {
            for (int r = warp; r < 128; r += 16) {
                float4 y = *(float4*)(Cs + r * CSTR + lane * 4);
                redv4(temp + (rowBase + r) * 128 + lane * 4, y);
            }
        }
        // next iteration's first sync protects Cs before restaging
    }
}

// ---------------- post: fp16 mma; feat = relu(gn2(relu(gn1(tmp)) @ ctr2_w) + feat_old) ----------------
__global__ __launch_bounds__(256, 2) void post_kernel(
    float* __restrict__ tmp, float* __restrict__ feat,
    const float* __restrict__ Bw,
    const float* __restrict__ ng, const float* __restrict__ nb,
    const float* __restrict__ g2, const float* __restrict__ b2,
    float* __restrict__ dout, int zero_tmp)
{
    extern __shared__ char smc[];
    uint32_t* As2 = (uint32_t*)(smc);
    uint32_t* Bs2 = (uint32_t*)(smc + 34816);
    float*    Cs  = (float*)(smc);                // union after GEMM

    int tid = threadIdx.x, lane = tid & 31, warp = tid >> 5;
    int gid = lane >> 2, tig = lane & 3;
    int wm = warp >> 1, wn = warp & 1;
    long rowBase = (long)blockIdx.x * 128;

    {
        int r = tid >> 1;
        int h = (tid & 1) * 64;
        float* xp = tmp + (rowBase + r) * 128 + h;
        float s = 0.f, sq = 0.f;
        float4 av[16];
#pragma unroll
        for (int j = 0; j < 16; j++) {
            av[j] = ld4(xp + j * 4);
            s  += av[j].x + av[j].y + av[j].z + av[j].w;
            sq += av[j].x * av[j].x + av[j].y * av[j].y + av[j].z * av[j].z + av[j].w * av[j].w;
        }
        s  += __shfl_xor_sync(0xffffffffu, s, 1);
        sq += __shfl_xor_sync(0xffffffffu, sq, 1);
        float mean = s * (1.f / 128.f);
        float kinv = rsqrtf(sq * (1.f / 128.f) - mean * mean + 1e-5f);
        int h2base = h >> 1;
#pragma unroll
        for (int j = 0; j < 16; j++) {
            int k = h + j * 4;
            float4 gg = ld4(ng + k), bb = ld4(nb + k);
            float ox = fmaxf((av[j].x - mean) * kinv * gg.x + bb.x, 0.f);
            float oy = fmaxf((av[j].y - mean) * kinv * gg.y + bb.y, 0.f);
            float oz = fmaxf((av[j].z - mean) * kinv * gg.z + bb.z, 0.f);
            float ow = fmaxf((av[j].w - mean) * kinv * gg.w + bb.w, 0.f);
            As2[(h2base + j * 2 + 0) * S2 + r] = h2(ox, oy);
            As2[(h2base + j * 2 + 1) * S2 + r] = h2(oz, ow);
        }
        if (zero_tmp) {
            float4 z = make_float4(0.f, 0.f, 0.f, 0.f);
#pragma unroll
            for (int j = 0; j < 16; j++) *(float4*)(xp + j * 4) = z;
        }
    }

#pragma unroll
    for (int j = 0; j < 8; j++) {
        int idx = tid + j * 256;
        int kp = idx >> 5, cg = (idx & 31) * 4;
        float4 lo = ld4(Bw + (2 * kp) * 128 + cg);
        float4 hi = ld4(Bw + (2 * kp + 1) * 128 + cg);
        uint4 v;
        v.x = h2(lo.x, hi.x);
        v.y = h2(lo.y, hi.y);
        v.z = h2(lo.z, hi.z);
        v.w = h2(lo.w, hi.w);
        *(uint4*)(Bs2 + kp * S2 + cg) = v;
    }
    __syncthreads();

    float acc[2][8][4];
#pragma unroll
    for (int tm = 0; tm < 2; tm++)
#pragma unroll
        for (int nt = 0; nt < 8; nt++)
#pragma unroll
            for (int j = 0; j < 4; j++) acc[tm][nt][j] = 0.f;

#pragma unroll
    for (int ks = 0; ks < 8; ks++) {
        int kk = ks * 8;
        uint32_t af[2][4];
#pragma unroll
        for (int tm = 0; tm < 2; tm++) {
            int rr = wm * 32 + tm * 16 + gid;
            const uint32_t* a0p = As2 + (kk + tig) * S2 + rr;
            const uint32_t* a1p = As2 + (kk + tig + 4) * S2 + rr;
            af[tm][0] = a0p[0];
            af[tm][1] = a0p[8];
            af[tm][2] = a1p[0];
            af[tm][3] = a1p[8];
        }
#pragma unroll
        for (int nt = 0; nt < 8; nt++) {
            int cc = wn * 64 + nt * 8 + gid;
            uint32_t b0 = Bs2[(kk + tig) * S2 + cc];
            uint32_t b1 = Bs2[(kk + tig + 4) * S2 + cc];
#pragma unroll
            for (int tm = 0; tm < 2; tm++)
                MMA_F16(acc[tm][nt], af[tm][0], af[tm][1], af[tm][2], af[tm][3], b0, b1);
        }
    }
    __syncthreads();

#pragma unroll
    for (int tm = 0; tm < 2; tm++) {
        int r0 = wm * 32 + tm * 16 + gid;
#pragma unroll
        for (int nt = 0; nt < 8; nt++) {
            int cc = wn * 64 + nt * 8 + tig * 2;
            *(float2*)(Cs + r0 * CSTR + cc)       = make_float2(acc[tm][nt][0], acc[tm][nt][1]);
            *(float2*)(Cs + (r0 + 8) * CSTR + cc) = make_float2(acc[tm][nt][2], acc[tm][nt][3]);
        }
    }
    __syncthreads();

    for (int r = warp; r < 128; r += 8) {
        int c = lane * 4;
        float4 x = *(float4*)(Cs + r * CSTR + c);
        float m, k;
        gn_stats(x, m, k);
        float4 gg = ld4(g2 + c), bb = ld4(b2 + c);
        long grow = rowBase + r;
        float4 old = ld4(feat + grow * 128 + c);
        float4 o;
        o.x = fmaxf((x.x - m) * k * gg.x + bb.x + old.x, 0.f);
        o.y = fmaxf((x.y - m) * k * gg.y + bb.y + old.y, 0.f);
        o.z = fmaxf((x.z - m) * k * gg.z + bb.z + old.z, 0.f);
        o.w = fmaxf((x.w - m) * k * gg.w + bb.w + old.w, 0.f);
        *(float4*)(feat + grow * 128 + c) = o;
        if (dout && grow < NN) *(float4*)(dout + grow * 128 + c) = o;
    }
}

// ---------------- host launcher ----------------
extern "C" void kernel_launch(void* const* d_in, const int* in_sizes, int n_in,
                              void* d_out, int out_size)
{
    const float* ctrs   = (const float*)d_in[0];
    const float* feats  = (const float*)d_in[1];
    const float* w_in1  = (const float*)d_in[2];
    const float* b_in1  = (const float*)d_in[3];
    const float* w_in2  = (const float*)d_in[4];
    const float* g_in   = (const float*)d_in[5];
    const float* be_in  = (const float*)d_in[6];
    const float* w_seg1 = (const float*)d_in[7];
    const float* b_seg1 = (const float*)d_in[8];
    const float* w_seg2 = (const float*)d_in[9];
    const float* g_seg  = (const float*)d_in[10];
    const float* be_seg = (const float*)d_in[11];
    const float* ctr_w  = (const float*)d_in[12];
    const float* pre_w  = (const float*)d_in[13];
    const float* suc_w  = (const float*)d_in[14];
    const float* left_w = (const float*)d_in[15];
    const float* right_w= (const float*)d_in[16];
    const float* norm_g = (const float*)d_in[17];
    const float* norm_b = (const float*)d_in[18];
    const float* ctr2_w = (const float*)d_in[19];
    const float* ctr2_g = (const float*)d_in[20];
    const float* ctr2_b = (const float*)d_in[21];
    const int* pre_u  = (const int*)d_in[22];
    const int* pre_v  = (const int*)d_in[23];
    const int* suc_u  = (const int*)d_in[24];
    const int* suc_v  = (const int*)d_in[25];
    const int* left_u = (const int*)d_in[26];
    const int* left_v = (const int*)d_in[27];
    const int* right_u= (const int*)d_in[28];
    const int* right_v= (const int*)d_in[29];

    float *feat, *tmp, *y;
    int *cnt;
    uint32_t *wimg;
    cudaGetSymbolAddress((void**)&feat, g_feat);
    cudaGetSymbolAddress((void**)&tmp,  g_tmp);
    cudaGetSymbolAddress((void**)&y,    g_y);
    cudaGetSymbolAddress((void**)&cnt,  g_cnt);
    cudaGetSymbolAddress((void**)&wimg, g_wimg);

    const int MAT = 128 * 128;
    const int EB = (TOTAL_E + 255) / 256;

    static bool attr_set = false;
    if (!attr_set) {
        cudaFuncSetAttribute(enc_gemm2_kernel, cudaFuncAttributeMaxDynamicSharedMemorySize, SMEM_ENC);
        cudaFuncSetAttribute(post_kernel,      cudaFuncAttributeMaxDynamicSharedMemorySize, SMEM_POST);
        cudaFuncSetAttribute(fuse_kernel,      cudaFuncAttributeMaxDynamicSharedMemorySize, SMEM_FUSE3);
        attr_set = true;
    }

    cudaMemsetAsync(cnt, 0, NBUCK * sizeof(int));
    place_kernel<<<EB, 256>>>(pre_u, pre_v, suc_u, suc_v, left_u, left_v, right_u, right_v);
    prep_kernel<<<60, 256>>>(pre_w, suc_w, left_w, right_w, ctr_w);

    enc1_kernel<<<(NN * 32) / 256, 256>>>(ctrs, feats, w_in1, b_in1, w_seg1, b_seg1, tmp, y);
    enc_gemm2_kernel<<<NBLK, 256, SMEM_ENC>>>(tmp, w_in2, y, w_seg2);
    enc2_kernel<<<NN / 8, 256>>>(tmp, g_in, be_in, y, g_seg, be_seg, feat);

    for (int i = 0; i < LL; i++) {
        fuse_kernel<<<NBLK, 512, SMEM_FUSE3>>>(feat, tmp, wimg + (size_t)i * 15 * IMGW);
        post_kernel<<<NBLK, 256, SMEM_POST>>>(
            tmp, feat, ctr2_w + (size_t)i * MAT,
            norm_g + i * 128, norm_b + i * 128,
            ctr2_g + i * 128, ctr2_b + i * 128,
            (i == LL - 1) ? (float*)d_out : nullptr,
            (i < LL - 1) ? 1 : 0);
    }
}

// round 11
// speedup vs baseline: 1.9370x; 1.1704x over previous
#include <cuda_runtime.h>
#include <cuda_fp16.h>
#include <cstdint>

#define NN 200000
#define NPAD 200064     // 1563 * 128
#define DD 128
#define EE 200000
#define EE2 20000
#define SS 6
#define LL 4
#define NBLK 1563
#define S2  136         // fp16 half2 smem stride (uint32 units) for scalar-LDS kernels
#define RSW 68          // row stride in words for ldmatrix layout (136 halves)
#define RSB 272         // row stride bytes
#define CSTR 132        // fp32 C stride (post kernel)
#define NTYPE 14
#define NBUCK (NTYPE * NBLK)
#define TOTAL_E (12 * EE + 2 * EE2)
#define CAP1 256
#define CAP2 64
#define EDGESZ (12 * NBLK * CAP1 + 2 * NBLK * CAP2)

#define IMGW (128 * RSW)        // uint32 words per prepped B image (8704)
#define IMGB (IMGW * 4)         // 34816 bytes
#define CHW  (128 * RSW)        // fp16 C buffer words (8704)
#define CHB  (CHW * 4)

// fuse smem layout (bytes)
#define F_A   0                          // A tile (ldmatrix layout): 34816
#define F_B   34816                      // B x2: 69632
#define F_C   (34816 + 69632)            // CH x2 (fp16): 69632
#define F_E   (34816 + 69632 + 69632)    // EIX: 12800
#define F_CNT (F_E + 12800)              // SCNT: 64
#define SMEM_FUSE4 (F_CNT + 64)          // 186944
#define SMEM_POST 69632
#define SMEM_ENC  69632

// ---------------- device scratch ----------------
__device__ float g_feat[NPAD * DD];
__device__ float g_y   [NPAD * DD];
__device__ float g_tmp [NPAD * DD];
__device__ int   g_cnt [NBUCK];
__device__ int   g_edges[EDGESZ];
__device__ uint32_t g_wimg[60 * IMGW];   // prepped fp16 B^T images, [n][k] row-major

__device__ __forceinline__ float4 ld4(const float* p) { return *(const float4*)(p); }

// pack (lo, hi) into b32 f16x2 (lower half = lo)
__device__ __forceinline__ uint32_t h2(float lo, float hi) {
    uint32_t r;
    asm("cvt.rn.f16x2.f32 %0, %1, %2;" : "=r"(r) : "f"(hi), "f"(lo));
    return r;
}

__device__ __forceinline__ float wsum(float s) {
#pragma unroll
    for (int o = 16; o; o >>= 1) s += __shfl_xor_sync(0xffffffffu, s, o);
    return s;
}

__device__ __forceinline__ void redv4(float* p, float4 y) {
    asm volatile("red.global.add.v4.f32 [%0], {%1,%2,%3,%4};"
                 :: "l"(p), "f"(y.x), "f"(y.y), "f"(y.z), "f"(y.w) : "memory");
}

__device__ __forceinline__ uint32_t smem_u32(const void* p) {
    uint32_t a;
    asm("{ .reg .u64 t; cvta.to.shared.u64 t, %1; cvt.u32.u64 %0, t; }" : "=r"(a) : "l"(p));
    return a;
}

__device__ __forceinline__ void cpa16(uint32_t dst, const void* src) {
    asm volatile("cp.async.cg.shared.global [%0], [%1], 16;" :: "r"(dst), "l"(src));
}
__device__ __forceinline__ void cp_commit() {
    asm volatile("cp.async.commit_group;" ::: "memory");
}
template<int N>
__device__ __forceinline__ void cp_wait() {
    asm volatile("cp.async.wait_group %0;" :: "n"(N) : "memory");
}

#define LDSM_X4(r0, r1, r2, r3, addr) \
    asm volatile("ldmatrix.sync.aligned.m8n8.x4.shared.b16 {%0,%1,%2,%3}, [%4];" \
                 : "=r"(r0), "=r"(r1), "=r"(r2), "=r"(r3) : "r"(addr))

#define MMA_F16(acc, a0, a1, a2, a3, b0, b1) \
    asm volatile( \
        "mma.sync.aligned.m16n8k16.row.col.f32.f16.f16.f32 " \
        "{%0,%1,%2,%3}, {%4,%5,%6,%7}, {%8,%9}, {%0,%1,%2,%3};\n" \
        : "+f"((acc)[0]), "+f"((acc)[1]), "+f"((acc)[2]), "+f"((acc)[3]) \
        : "r"(a0), "r"(a1), "r"(a2), "r"(a3), "r"(b0), "r"(b1))

// ---------------- weight prep: fp32 W[k][n] -> fp16 image W^T [n][k], stride RSW ----------------
__global__ __launch_bounds__(256) void prep_kernel(
    const float* __restrict__ pre_w, const float* __restrict__ suc_w,
    const float* __restrict__ left_w, const float* __restrict__ right_w,
    const float* __restrict__ ctr_w)
{
    int m = blockIdx.x;              // 0..59
    int i = m / 15, t = m % 15;
    const float* W;
    if (t < 6)        W = pre_w  + (size_t)(i * 6 + t) * 16384;
    else if (t < 12)  W = suc_w  + (size_t)(i * 6 + (t - 6)) * 16384;
    else if (t == 12) W = left_w  + (size_t)i * 16384;
    else if (t == 13) W = right_w + (size_t)i * 16384;
    else              W = ctr_w   + (size_t)i * 16384;
    uint32_t* img = g_wimg + (size_t)m * IMGW;

    for (int e = threadIdx.x; e < 128 * 64; e += 256) {
        int n = e >> 6, kp = e & 63;
        img[n * RSW + kp] = h2(__ldg(&W[(2 * kp) * 128 + n]), __ldg(&W[(2 * kp + 1) * 128 + n]));
    }
}

// ---------------- edge buckets (type, v-block); relies on g_cnt zeroed ----------------
__global__ void place_kernel(const int* __restrict__ pre_u, const int* __restrict__ pre_v,
                             const int* __restrict__ suc_u, const int* __restrict__ suc_v,
                             const int* __restrict__ left_u, const int* __restrict__ left_v,
                             const int* __restrict__ right_u, const int* __restrict__ right_v)
{
    int idx = blockIdx.x * 256 + threadIdx.x;
    int t, u, v;
    if (idx < 6 * EE)            { t = idx / EE; u = pre_u[idx]; v = pre_v[idx]; }
    else if (idx < 12 * EE)      { int j = idx - 6 * EE; t = idx / EE; u = suc_u[j]; v = suc_v[j]; }
    else if (idx < 12 * EE + EE2){ int j = idx - 12 * EE; t = 12; u = left_u[j]; v = left_v[j]; }
    else if (idx < TOTAL_E)      { int j = idx - 12 * EE - EE2; t = 13; u = right_u[j]; v = right_v[j]; }
    else return;
    int vb = v >> 7;
    int b = t * NBLK + vb;
    int cap  = (t < 12) ? CAP1 : CAP2;
    int base = (t < 12) ? b * CAP1 : (12 * NBLK * CAP1 + ((t - 12) * NBLK + vb) * CAP2);
    int pos = atomicAdd(&g_cnt[b], 1);
    if (pos < cap) g_edges[base + pos] = u | ((v & 127) << 18);
}

// ---------------- encoder stage 1 ----------------
__global__ __launch_bounds__(256) void enc1_kernel(
    const float* __restrict__ ctrs, const float* __restrict__ feats,
    const float* __restrict__ w_in1, const float* __restrict__ b_in1,
    const float* __restrict__ w_seg1, const float* __restrict__ b_seg1,
    float* __restrict__ h_in, float* __restrict__ h_seg)
{
    int idx = blockIdx.x * blockDim.x + threadIdx.x;
    int n = idx >> 5;
    if (n >= NN) return;
    int c = (idx & 31) * 4;

    float c0 = __ldg(&ctrs[2 * n]),  c1 = __ldg(&ctrs[2 * n + 1]);
    float f0 = __ldg(&feats[2 * n]), f1 = __ldg(&feats[2 * n + 1]);

    float4 wi0 = ld4(w_in1 + c), wi1 = ld4(w_in1 + DD + c), bi = ld4(b_in1 + c);
    float4 ws0 = ld4(w_seg1 + c), ws1 = ld4(w_seg1 + DD + c), bs = ld4(b_seg1 + c);

    float4 hi, hs;
    hi.x = fmaxf(c0 * wi0.x + c1 * wi1.x + bi.x, 0.f);
    hi.y = fmaxf(c0 * wi0.y + c1 * wi1.y + bi.y, 0.f);
    hi.z = fmaxf(c0 * wi0.z + c1 * wi1.z + bi.z, 0.f);
    hi.w = fmaxf(c0 * wi0.w + c1 * wi1.w + bi.w, 0.f);
    hs.x = fmaxf(f0 * ws0.x + f1 * ws1.x + bs.x, 0.f);
    hs.y = fmaxf(f0 * ws0.y + f1 * ws1.y + bs.y, 0.f);
    hs.z = fmaxf(f0 * ws0.z + f1 * ws1.z + bs.z, 0.f);
    hs.w = fmaxf(f0 * ws0.w + f1 * ws1.w + bs.w, 0.f);

    *(float4*)&h_in [n * DD + c] = hi;
    *(float4*)&h_seg[n * DD + c] = hs;
}

// ---------------- encoder GEMM pair (fp16 mma, in-place) ----------------
__global__ __launch_bounds__(256, 2) void enc_gemm2_kernel(
    float* __restrict__ Ain, const float* __restrict__ Ba,
    float* __restrict__ Aseg, const float* __restrict__ Bb)
{
    extern __shared__ char smc[];
    uint32_t* As2 = (uint32_t*)(smc);             // [64 kpair][S2]
    uint32_t* Bs2 = (uint32_t*)(smc + 34816);

    int tid = threadIdx.x, lane = tid & 31, warp = tid >> 5;
    int gid = lane >> 2, tig = lane & 3;
    int wm = warp >> 1, wn = warp & 1;            // 4x2 grid, warp tile 32x64
    long rowBase = (long)blockIdx.x * 128;

    for (int p = 0; p < 2; p++) {
        float* A = p ? Aseg : Ain;
        const float* B = p ? Bb : Ba;

        {
            int r = tid >> 1;
            int h = (tid & 1) * 64;
            const float* ap = A + (rowBase + r) * 128 + h;
            int hb = h >> 1;
#pragma unroll
            for (int j = 0; j < 16; j++) {
                float4 a = ld4(ap + j * 4);
                As2[(hb + j * 2 + 0) * S2 + r] = h2(a.x, a.y);
                As2[(hb + j * 2 + 1) * S2 + r] = h2(a.z, a.w);
            }
        }
#pragma unroll
        for (int j = 0; j < 8; j++) {
            int idx = tid + j * 256;
            int kp = idx >> 5, cg = (idx & 31) * 4;
            float4 lo = ld4(B + (2 * kp) * 128 + cg);
            float4 hi = ld4(B + (2 * kp + 1) * 128 + cg);
            uint4 v;
            v.x = h2(lo.x, hi.x);
            v.y = h2(lo.y, hi.y);
            v.z = h2(lo.z, hi.z);
            v.w = h2(lo.w, hi.w);
            *(uint4*)(Bs2 + kp * S2 + cg) = v;
        }
        __syncthreads();

        float acc[2][8][4];
#pragma unroll
        for (int tm = 0; tm < 2; tm++)
#pragma unroll
            for (int nt = 0; nt < 8; nt++)
#pragma unroll
                for (int j = 0; j < 4; j++) acc[tm][nt][j] = 0.f;

#pragma unroll
        for (int ks = 0; ks < 8; ks++) {
            int kk = ks * 8;
            uint32_t af[2][4];
#pragma unroll
            for (int tm = 0; tm < 2; tm++) {
                int rr = wm * 32 + tm * 16 + gid;
                const uint32_t* a0p = As2 + (kk + tig) * S2 + rr;
                const uint32_t* a1p = As2 + (kk + tig + 4) * S2 + rr;
                af[tm][0] = a0p[0];
                af[tm][1] = a0p[8];
                af[tm][2] = a1p[0];
                af[tm][3] = a1p[8];
            }
#pragma unroll
            for (int nt = 0; nt < 8; nt++) {
                int cc = wn * 64 + nt * 8 + gid;
                uint32_t b0 = Bs2[(kk + tig) * S2 + cc];
                uint32_t b1 = Bs2[(kk + tig + 4) * S2 + cc];
#pragma unroll
                for (int tm = 0; tm < 2; tm++)
                    MMA_F16(acc[tm][nt], af[tm][0], af[tm][1], af[tm][2], af[tm][3], b0, b1);
            }
        }
        __syncthreads();

#pragma unroll
        for (int tm = 0; tm < 2; tm++) {
            long r0 = rowBase + wm * 32 + tm * 16 + gid;
#pragma unroll
            for (int nt = 0; nt < 8; nt++) {
                int cc = wn * 64 + nt * 8 + tig * 2;
                *(float2*)(A + r0 * 128 + cc)       = make_float2(acc[tm][nt][0], acc[tm][nt][1]);
                *(float2*)(A + (r0 + 8) * 128 + cc) = make_float2(acc[tm][nt][2], acc[tm][nt][3]);
            }
        }
        __syncthreads();
    }
}

// ---------------- GN helpers ----------------
__device__ __forceinline__ void gn_stats(float4 x, float& mean, float& kinv) {
    float s  = x.x + x.y + x.z + x.w;
    float sq = x.x * x.x + x.y * x.y + x.z * x.z + x.w * x.w;
    s  = wsum(s)  * (1.f / 128.f);
    sq = wsum(sq) * (1.f / 128.f);
    mean = s;
    float var = sq - s * s;
    kinv = rsqrtf(var + 1e-5f);
}

// enc2: feat = relu(gn(A) + gn(B)); zero A rows (tmp) for iter 0
__global__ __launch_bounds__(256) void enc2_kernel(
    float* __restrict__ A, const float* __restrict__ gA, const float* __restrict__ bA,
    const float* __restrict__ Bv, const float* __restrict__ gB, const float* __restrict__ bB,
    float* __restrict__ feat)
{
    int row = blockIdx.x * 8 + (threadIdx.x >> 5);
    if (row >= NN) return;
    int lane = threadIdx.x & 31;
    int c = lane * 4;
    float4 a = ld4(&A[(long)row * 128 + c]);
    float4 b = ld4(&Bv[(long)row * 128 + c]);
    float ma, ka, mb, kb;
    gn_stats(a, ma, ka);
    gn_stats(b, mb, kb);
    float4 ga = ld4(gA + c), ba = ld4(bA + c);
    float4 gb = ld4(gB + c), bb = ld4(bB + c);
    float4 o;
    o.x = fmaxf((a.x - ma) * ka * ga.x + ba.x + (b.x - mb) * kb * gb.x + bb.x, 0.f);
    o.y = fmaxf((a.y - ma) * ka * ga.y + ba.y + (b.y - mb) * kb * gb.y + bb.y, 0.f);
    o.z = fmaxf((a.z - ma) * ka * ga.z + ba.z + (b.z - mb) * kb * gb.z + bb.z, 0.f);
    o.w = fmaxf((a.w - ma) * ka * ga.w + ba.w + (b.w - mb) * kb * gb.w + bb.w, 0.f);
    *(float4*)&feat[(long)row * 128 + c] = o;
    *(float4*)&A   [(long)row * 128 + c] = make_float4(0.f, 0.f, 0.f, 0.f);
}

// ---------------- fused message-passing kernel (fp16 mma + ldmatrix, 1-sync pipeline) ----------------
__global__ __launch_bounds__(512) void fuse_kernel(
    const float* __restrict__ featIn, float* __restrict__ temp,
    const uint32_t* __restrict__ Wimg)
{
    extern __shared__ char smc[];
    uint32_t* CH  = (uint32_t*)(smc + F_C);   // 2 fp16 C buffers [128][RSW words]
    int*      EIX = (int*)(smc + F_E);
    int*      SCNT= (int*)(smc + F_CNT);

    uint32_t sb = smem_u32(smc);
    uint32_t eixA = sb + F_E;

    int tid = threadIdx.x, lane = tid & 31, warp = tid >> 5;
    int gid = lane >> 2, tig = lane & 3;
    int wm = warp >> 2, wn = warp & 3;            // 4x4 warp grid, tile 32x32
    int bid = blockIdx.x;
    long rowBase = (long)bid * 128;

    // --- async group 0: edge indices + B(0) ---
    for (int ch = tid; ch < 800; ch += 512) {
        int w = ch * 4;
        int srcw;
        if (w < 3072) {
            int t = w >> 8, off = w & 255;
            srcw = (t * NBLK + bid) * CAP1 + off;
        } else {
            int j = w - 3072;
            int t = j >> 6, off = j & 63;
            srcw = 12 * NBLK * CAP1 + (t * NBLK + bid) * CAP2 + off;
        }
        cpa16(eixA + w * 4, g_edges + srcw);
    }
    for (int ch = tid; ch < IMGB / 16; ch += 512)
        cpa16(sb + F_B + ch * 16, (const char*)Wimg + ch * 16);
    cp_commit();

    // --- bucket counts -> smem ---
    if (tid < 14) {
        int c = g_cnt[tid * NBLK + bid];
        int cap = (tid < 12) ? CAP1 : CAP2;
        SCNT[tid] = (c > cap) ? cap : c;
    }

    // --- A tile: row-major fp16 [row][k], stride RSW words ---
    {
        int r = tid >> 2, q = tid & 3;
        const float* ap = featIn + (rowBase + r) * 128 + q * 32;
        char* dst = smc + F_A + r * RSB + q * 64;
#pragma unroll
        for (int j = 0; j < 8; j++) {
            float4 a = ld4(ap + j * 4);
            uint2 v;
            v.x = h2(a.x, a.y);
            v.y = h2(a.z, a.w);
            *(uint2*)(dst + j * 8) = v;
        }
    }

    // per-warp ldmatrix base addresses
    uint32_t aBase = sb + F_A
        + (uint32_t)(wm * 32 + (lane & 7) + ((lane & 8) ? 8 : 0)) * RSB
        + ((lane & 16) ? 16 : 0);
    uint32_t bBase = sb + F_B
        + (uint32_t)(wn * 32 + (lane & 7) + ((lane & 16) ? 8 : 0)) * RSB
        + ((lane & 8) ? 16 : 0);

    for (int t = 0; t < 15; t++) {
        cp_wait<0>();
        __syncthreads();   // B(t) visible; C(t-1) staged; scatter(t-2) reads of CH[t&1] done

        // issue B(t+1) into other buffer
        if (t < 14) {
            const char* src = (const char*)(Wimg + (size_t)(t + 1) * IMGW);
            uint32_t dst = sb + F_B + ((t + 1) & 1) * IMGB;
            for (int ch = tid; ch < IMGB / 16; ch += 512)
                cpa16(dst + ch * 16, src + ch * 16);
            cp_commit();
        }

        // scatter(t-1): reds overlap with GEMM(t) below
        if (t > 0) {
            int s = t - 1;
            int len = SCNT[s];
            int ebase = (s < 12) ? s * CAP1 : 3072 + (s - 12) * CAP2;
            const uint32_t* Crow = CH + ((s & 1) ? CHW : 0);
            for (int e = warp; e < len; e += 16) {
                int pk = EIX[ebase + e];
                int u  = pk & 0x3FFFF;
                int vl = pk >> 18;
                uint2 w = *(const uint2*)(Crow + vl * RSW + lane * 2);
                float2 f0 = __half22float2(*(__half2*)&w.x);
                float2 f1 = __half22float2(*(__half2*)&w.y);
                redv4(temp + (long)u * 128 + lane * 4, make_float4(f0.x, f0.y, f1.x, f1.y));
            }
        }

        // GEMM(t)
        uint32_t bOff = (uint32_t)(t & 1) * IMGB;
        float acc[2][4][4];
#pragma unroll
        for (int tm = 0; tm < 2; tm++)
#pragma unroll
            for (int nt = 0; nt < 4; nt++)
#pragma unroll
                for (int j = 0; j < 4; j++) acc[tm][nt][j] = 0.f;

#pragma unroll
        for (int ks = 0; ks < 8; ks++) {
            uint32_t af0[4], af1[4], bf0[4], bf1[4];
            LDSM_X4(af0[0], af0[1], af0[2], af0[3], aBase + ks * 32);
            LDSM_X4(af1[0], af1[1], af1[2], af1[3], aBase + 16 * RSB + ks * 32);
            LDSM_X4(bf0[0], bf0[1], bf0[2], bf0[3], bBase + bOff + ks * 32);
            LDSM_X4(bf1[0], bf1[1], bf1[2], bf1[3], bBase + bOff + 16 * RSB + ks * 32);

            MMA_F16(acc[0][0], af0[0], af0[1], af0[2], af0[3], bf0[0], bf0[1]);
            MMA_F16(acc[1][0], af1[0], af1[1], af1[2], af1[3], bf0[0], bf0[1]);
            MMA_F16(acc[0][1], af0[0], af0[1], af0[2], af0[3], bf0[2], bf0[3]);
            MMA_F16(acc[1][1], af1[0], af1[1], af1[2], af1[3], bf0[2], bf0[3]);
            MMA_F16(acc[0][2], af0[0], af0[1], af0[2], af0[3], bf1[0], bf1[1]);
            MMA_F16(acc[1][2], af1[0], af1[1], af1[2], af1[3], bf1[0], bf1[1]);
            MMA_F16(acc[0][3], af0[0], af0[1], af0[2], af0[3], bf1[2], bf1[3]);
            MMA_F16(acc[1][3], af1[0], af1[1], af1[2], af1[3], bf1[2], bf1[3]);
        }

        // stage C(t) as fp16 into CH[t&1] (warp-owned rows; safe pre-sync)
        {
            uint32_t* Cw = CH + ((t & 1) ? CHW : 0);
#pragma unroll
            for (int tm = 0; tm < 2; tm++) {
                int r0 = wm * 32 + tm * 16 + gid;
#pragma unroll
                for (int nt = 0; nt < 4; nt++) {
                    int widx = wn * 16 + nt * 4 + tig;
                    Cw[r0 * RSW + widx]       = h2(acc[tm][nt][0], acc[tm][nt][1]);
                    Cw[(r0 + 8) * RSW + widx] = h2(acc[tm][nt][2], acc[tm][nt][3]);
                }
            }
        }
    }

    // epilogue: scatter(14) = ctr row-add from CH[0]
    __syncthreads();
    for (int r = warp; r < 128; r += 16) {
        uint2 w = *(const uint2*)(CH + r * RSW + lane * 2);
        float2 f0 = __half22float2(*(__half2*)&w.x);
        float2 f1 = __half22float2(*(__half2*)&w.y);
        redv4(temp + (rowBase + r) * 128 + lane * 4, make_float4(f0.x, f0.y, f1.x, f1.y));
    }
}

// ---------------- post: fp16 mma; feat = relu(gn2(relu(gn1(tmp)) @ ctr2_w) + feat_old) ----------------
__global__ __launch_bounds__(256, 2) void post_kernel(
    float* __restrict__ tmp, float* __restrict__ feat,
    const float* __restrict__ Bw,
    const float* __restrict__ ng, const float* __restrict__ nb,
    const float* __restrict__ g2, const float* __restrict__ b2,
    float* __restrict__ dout, int zero_tmp, int zero_cnt)
{
    extern __shared__ char smc[];
    uint32_t* As2 = (uint32_t*)(smc);
    uint32_t* Bs2 = (uint32_t*)(smc + 34816);
    float*    Cs  = (float*)(smc);                // union after GEMM

    int tid = threadIdx.x, lane = tid & 31, warp = tid >> 5;
    int gid = lane >> 2, tig = lane & 3;
    int wm = warp >> 1, wn = warp & 1;
    long rowBase = (long)blockIdx.x * 128;

    // restore bucket counters for next replay (last iteration only)
    if (zero_cnt) {
        for (int i = blockIdx.x * 14 + tid; i < NBUCK && tid < 14; i += 0) {
            g_cnt[i] = 0;
            break;
        }
        // simpler grid-stride form:
    }
    if (zero_cnt && tid < 16) {
        int i = blockIdx.x * 16 + tid;
        if (i < NBUCK) g_cnt[i] = 0;
        i += NBLK * 16;
        if (i < NBUCK) g_cnt[i] = 0;
    }

    {
        int r = tid >> 1;
        int h = (tid & 1) * 64;
        float* xp = tmp + (rowBase + r) * 128 + h;
        float s = 0.f, sq = 0.f;
        float4 av[16];
#pragma unroll
        for (int j = 0; j < 16; j++) {
            av[j] = ld4(xp + j * 4);
            s  += av[j].x + av[j].y + av[j].z + av[j].w;
            sq += av[j].x * av[j].x + av[j].y * av[j].y + av[j].z * av[j].z + av[j].w * av[j].w;
        }
        s  += __shfl_xor_sync(0xffffffffu, s, 1);
        sq += __shfl_xor_sync(0xffffffffu, sq, 1);
        float mean = s * (1.f / 128.f);
        float kinv = rsqrtf(sq * (1.f / 128.f) - mean * mean + 1e-5f);
        int h2base = h >> 1;
#pragma unroll
        for (int j = 0; j < 16; j++) {
            int k = h + j * 4;
            float4 gg = ld4(ng + k), bb = ld4(nb + k);
            float ox = fmaxf((av[j].x - mean) * kinv * gg.x + bb.x, 0.f);
            float oy = fmaxf((av[j].y - mean) * kinv * gg.y + bb.y, 0.f);
            float oz = fmaxf((av[j].z - mean) * kinv * gg.z + bb.z, 0.f);
            float ow = fmaxf((av[j].w - mean) * kinv * gg.w + bb.w, 0.f);
            As2[(h2base + j * 2 + 0) * S2 + r] = h2(ox, oy);
            As2[(h2base + j * 2 + 1) * S2 + r] = h2(oz, ow);
        }
        if (zero_tmp) {
            float4 z = make_float4(0.f, 0.f, 0.f, 0.f);
#pragma unroll
            for (int j = 0; j < 16; j++) *(float4*)(xp + j * 4) = z;
        }
    }

#pragma unroll
    for (int j = 0; j < 8; j++) {
        int idx = tid + j * 256;
        int kp = idx >> 5, cg = (idx & 31) * 4;
        float4 lo = ld4(Bw + (2 * kp) * 128 + cg);
        float4 hi = ld4(Bw + (2 * kp + 1) * 128 + cg);
        uint4 v;
        v.x = h2(lo.x, hi.x);
        v.y = h2(lo.y, hi.y);
        v.z = h2(lo.z, hi.z);
        v.w = h2(lo.w, hi.w);
        *(uint4*)(Bs2 + kp * S2 + cg) = v;
    }
    __syncthreads();

    float acc[2][8][4];
#pragma unroll
    for (int tm = 0; tm < 2; tm++)
#pragma unroll
        for (int nt = 0; nt < 8; nt++)
#pragma unroll
            for (int j = 0; j < 4; j++) acc[tm][nt][j] = 0.f;

#pragma unroll
    for (int ks = 0; ks < 8; ks++) {
        int kk = ks * 8;
        uint32_t af[2][4];
#pragma unroll
        for (int tm = 0; tm < 2; tm++) {
            int rr = wm * 32 + tm * 16 + gid;
            const uint32_t* a0p = As2 + (kk + tig) * S2 + rr;
            const uint32_t* a1p = As2 + (kk + tig + 4) * S2 + rr;
            af[tm][0] = a0p[0];
            af[tm][1] = a0p[8];
            af[tm][2] = a1p[0];
            af[tm][3] = a1p[8];
        }
#pragma unroll
        for (int nt = 0; nt < 8; nt++) {
            int cc = wn * 64 + nt * 8 + gid;
            uint32_t b0 = Bs2[(kk + tig) * S2 + cc];
            uint32_t b1 = Bs2[(kk + tig + 4) * S2 + cc];
#pragma unroll
            for (int tm = 0; tm < 2; tm++)
                MMA_F16(acc[tm][nt], af[tm][0], af[tm][1], af[tm][2], af[tm][3], b0, b1);
        }
    }
    __syncthreads();

#pragma unroll
    for (int tm = 0; tm < 2; tm++) {
        int r0 = wm * 32 + tm * 16 + gid;
#pragma unroll
        for (int nt = 0; nt < 8; nt++) {
            int cc = wn * 64 + nt * 8 + tig * 2;
            *(float2*)(Cs + r0 * CSTR + cc)       = make_float2(acc[tm][nt][0], acc[tm][nt][1]);
            *(float2*)(Cs + (r0 + 8) * CSTR + cc) = make_float2(acc[tm][nt][2], acc[tm][nt][3]);
        }
    }
    __syncthreads();

    for (int r = warp; r < 128; r += 8) {
        int c = lane * 4;
        float4 x = *(float4*)(Cs + r * CSTR + c);
        float m, k;
        gn_stats(x, m, k);
        float4 gg = ld4(g2 + c), bb = ld4(b2 + c);
        long grow = rowBase + r;
        float4 old = ld4(feat + grow * 128 + c);
        float4 o;
        o.x = fmaxf((x.x - m) * k * gg.x + bb.x + old.x, 0.f);
        o.y = fmaxf((x.y - m) * k * gg.y + bb.y + old.y, 0.f);
        o.z = fmaxf((x.z - m) * k * gg.z + bb.z + old.z, 0.f);
        o.w = fmaxf((x.w - m) * k * gg.w + bb.w + old.w, 0.f);
        *(float4*)(feat + grow * 128 + c) = o;
        if (dout && grow < NN) *(float4*)(dout + grow * 128 + c) = o;
    }
}

// ---------------- host launcher ----------------
extern "C" void kernel_launch(void* const* d_in, const int* in_sizes, int n_in,
                              void* d_out, int out_size)
{
    const float* ctrs   = (const float*)d_in[0];
    const float* feats  = (const float*)d_in[1];
    const float* w_in1  = (const float*)d_in[2];
    const float* b_in1  = (const float*)d_in[3];
    const float* w_in2  = (const float*)d_in[4];
    const float* g_in   = (const float*)d_in[5];
    const float* be_in  = (const float*)d_in[6];
    const float* w_seg1 = (const float*)d_in[7];
    const float* b_seg1 = (const float*)d_in[8];
    const float* w_seg2 = (const float*)d_in[9];
    const float* g_seg  = (const float*)d_in[10];
    const float* be_seg = (const float*)d_in[11];
    const float* ctr_w  = (const float*)d_in[12];
    const float* pre_w  = (const float*)d_in[13];
    const float* suc_w  = (const float*)d_in[14];
    const float* left_w = (const float*)d_in[15];
    const float* right_w= (const float*)d_in[16];
    const float* norm_g = (const float*)d_in[17];
    const float* norm_b = (const float*)d_in[18];
    const float* ctr2_w = (const float*)d_in[19];
    const float* ctr2_g = (const float*)d_in[20];
    const float* ctr2_b = (const float*)d_in[21];
    const int* pre_u  = (const int*)d_in[22];
    const int* pre_v  = (const int*)d_in[23];
    const int* suc_u  = (const int*)d_in[24];
    const int* suc_v  = (const int*)d_in[25];
    const int* left_u = (const int*)d_in[26];
    const int* left_v = (const int*)d_in[27];
    const int* right_u= (const int*)d_in[28];
    const int* right_v= (const int*)d_in[29];

    float *feat, *tmp, *y;
    uint32_t *wimg;
    cudaGetSymbolAddress((void**)&feat, g_feat);
    cudaGetSymbolAddress((void**)&tmp,  g_tmp);
    cudaGetSymbolAddress((void**)&y,    g_y);
    cudaGetSymbolAddress((void**)&wimg, g_wimg);

    const int MAT = 128 * 128;
    const int EB = (TOTAL_E + 255) / 256;

    static bool attr_set = false;
    if (!attr_set) {
        cudaFuncSetAttribute(enc_gemm2_kernel, cudaFuncAttributeMaxDynamicSharedMemorySize, SMEM_ENC);
        cudaFuncSetAttribute(post_kernel,      cudaFuncAttributeMaxDynamicSharedMemorySize, SMEM_POST);
        cudaFuncSetAttribute(fuse_kernel,      cudaFuncAttributeMaxDynamicSharedMemorySize, SMEM_FUSE4);
        attr_set = true;
    }

    // g_cnt is zero: zero-initialized at module load; re-zeroed by post(i=3) each call.
    place_kernel<<<EB, 256>>>(pre_u, pre_v, suc_u, suc_v, left_u, left_v, right_u, right_v);
    prep_kernel<<<60, 256>>>(pre_w, suc_w, left_w, right_w, ctr_w);

    enc1_kernel<<<(NN * 32) / 256, 256>>>(ctrs, feats, w_in1, b_in1, w_seg1, b_seg1, tmp, y);
    enc_gemm2_kernel<<<NBLK, 256, SMEM_ENC>>>(tmp, w_in2, y, w_seg2);
    enc2_kernel<<<NN / 8, 256>>>(tmp, g_in, be_in, y, g_seg, be_seg, feat);

    for (int i = 0; i < LL; i++) {
        fuse_kernel<<<NBLK, 512, SMEM_FUSE4>>>(feat, tmp, wimg + (size_t)i * 15 * IMGW);
        post_kernel<<<NBLK, 256, SMEM_POST>>>(
            tmp, feat, ctr2_w + (size_t)i * MAT,
            norm_g + i * 128, norm_b + i * 128,
            ctr2_g + i * 128, ctr2_b + i * 128,
            (i == LL - 1) ? (float*)d_out : nullptr,
            (i < LL - 1) ? 1 : 0,
            (i == LL - 1) ? 1 : 0);
    }
}

// round 12
// speedup vs baseline: 1.9480x; 1.0057x over previous
#include <cuda_runtime.h>
#include <cuda_fp16.h>
#include <cstdint>

#define NN 200000
#define NPAD 200064     // 1563 * 128
#define DD 128
#define EE 200000
#define EE2 20000
#define SS 6
#define LL 4
#define NBLK 1563
#define S2  136         // fp16 half2 smem stride (uint32 units) for scalar-LDS kernels
#define RSW 68          // row stride in words for ldmatrix layout (136 halves)
#define RSB 272         // row stride bytes
#define CSTR 132        // fp32 C stride (post kernel)
#define NTYPE 14
#define NBUCK (NTYPE * NBLK)
#define TOTAL_E (12 * EE + 2 * EE2)
#define CAP1 256
#define CAP2 64
#define EDGESZ (12 * NBLK * CAP1 + 2 * NBLK * CAP2)

#define IMGW (128 * RSW)        // uint32 words per prepped B image (8704)
#define IMGB (IMGW * 4)         // 34816 bytes
#define CHW  (128 * RSW)        // fp16 C buffer words
#define NIMG 16                 // images per layer: 15 fuse types + ctr2

// fuse smem layout (bytes)
#define F_A   0                          // A tile (ldmatrix layout): 34816
#define F_B   34816                      // B x2: 69632
#define F_C   (34816 + 69632)            // CH x2 (fp16): 69632
#define F_E   (34816 + 69632 + 69632)    // EIX: 12800
#define F_CNT (F_E + 12800)              // SCNT: 64
#define SMEM_FUSE4 (F_CNT + 64)          // 186944
#define SMEM_POST 69632
#define SMEM_ENC  69632

// ---------------- device scratch ----------------
__device__ float g_feat[NPAD * DD];
__device__ float g_y   [NPAD * DD];
__device__ float g_tmp [NPAD * DD];
__device__ int   g_cnt [NBUCK];
__device__ int   g_edges[EDGESZ];
__device__ uint32_t g_wimg[4 * NIMG * IMGW];   // prepped fp16 B^T images, [n][k] row-major

__device__ __forceinline__ float4 ld4(const float* p) { return *(const float4*)(p); }

// pack (lo, hi) into b32 f16x2 (lower half = lo)
__device__ __forceinline__ uint32_t h2(float lo, float hi) {
    uint32_t r;
    asm("cvt.rn.f16x2.f32 %0, %1, %2;" : "=r"(r) : "f"(hi), "f"(lo));
    return r;
}

__device__ __forceinline__ float wsum(float s) {
#pragma unroll
    for (int o = 16; o; o >>= 1) s += __shfl_xor_sync(0xffffffffu, s, o);
    return s;
}

__device__ __forceinline__ void redv4(float* p, float4 y) {
    asm volatile("red.global.add.v4.f32 [%0], {%1,%2,%3,%4};"
                 :: "l"(p), "f"(y.x), "f"(y.y), "f"(y.z), "f"(y.w) : "memory");
}

__device__ __forceinline__ uint32_t smem_u32(const void* p) {
    uint32_t a;
    asm("{ .reg .u64 t; cvta.to.shared.u64 t, %1; cvt.u32.u64 %0, t; }" : "=r"(a) : "l"(p));
    return a;
}

__device__ __forceinline__ void cpa16(uint32_t dst, const void* src) {
    asm volatile("cp.async.cg.shared.global [%0], [%1], 16;" :: "r"(dst), "l"(src));
}
__device__ __forceinline__ void cp_commit() {
    asm volatile("cp.async.commit_group;" ::: "memory");
}
template<int N>
__device__ __forceinline__ void cp_wait() {
    asm volatile("cp.async.wait_group %0;" :: "n"(N) : "memory");
}

#define LDSM_X4(r0, r1, r2, r3, addr) \
    asm volatile("ldmatrix.sync.aligned.m8n8.x4.shared.b16 {%0,%1,%2,%3}, [%4];" \
                 : "=r"(r0), "=r"(r1), "=r"(r2), "=r"(r3) : "r"(addr))

#define MMA_F16(acc, a0, a1, a2, a3, b0, b1) \
    asm volatile( \
        "mma.sync.aligned.m16n8k16.row.col.f32.f16.f16.f32 " \
        "{%0,%1,%2,%3}, {%4,%5,%6,%7}, {%8,%9}, {%0,%1,%2,%3};\n" \
        : "+f"((acc)[0]), "+f"((acc)[1]), "+f"((acc)[2]), "+f"((acc)[3]) \
        : "r"(a0), "r"(a1), "r"(a2), "r"(a3), "r"(b0), "r"(b1))

// ---------------- weight prep: fp32 W[k][n] -> fp16 image W^T [n][k], stride RSW ----------------
__global__ __launch_bounds__(256) void prep_kernel(
    const float* __restrict__ pre_w, const float* __restrict__ suc_w,
    const float* __restrict__ left_w, const float* __restrict__ right_w,
    const float* __restrict__ ctr_w, const float* __restrict__ ctr2_w)
{
    int m = blockIdx.x;              // 0..63
    int i = m >> 4, t = m & 15;
    const float* W;
    if (t < 6)        W = pre_w  + (size_t)(i * 6 + t) * 16384;
    else if (t < 12)  W = suc_w  + (size_t)(i * 6 + (t - 6)) * 16384;
    else if (t == 12) W = left_w  + (size_t)i * 16384;
    else if (t == 13) W = right_w + (size_t)i * 16384;
    else if (t == 14) W = ctr_w   + (size_t)i * 16384;
    else              W = ctr2_w  + (size_t)i * 16384;
    uint32_t* img = g_wimg + (size_t)m * IMGW;

    for (int e = threadIdx.x; e < 128 * 64; e += 256) {
        int n = e >> 6, kp = e & 63;
        img[n * RSW + kp] = h2(__ldg(&W[(2 * kp) * 128 + n]), __ldg(&W[(2 * kp + 1) * 128 + n]));
    }
}

// ---------------- edge buckets (type, v-block); relies on g_cnt zeroed ----------------
__global__ void place_kernel(const int* __restrict__ pre_u, const int* __restrict__ pre_v,
                             const int* __restrict__ suc_u, const int* __restrict__ suc_v,
                             const int* __restrict__ left_u, const int* __restrict__ left_v,
                             const int* __restrict__ right_u, const int* __restrict__ right_v)
{
    int idx = blockIdx.x * 256 + threadIdx.x;
    int t, u, v;
    if (idx < 6 * EE)            { t = idx / EE; u = pre_u[idx]; v = pre_v[idx]; }
    else if (idx < 12 * EE)      { int j = idx - 6 * EE; t = idx / EE; u = suc_u[j]; v = suc_v[j]; }
    else if (idx < 12 * EE + EE2){ int j = idx - 12 * EE; t = 12; u = left_u[j]; v = left_v[j]; }
    else if (idx < TOTAL_E)      { int j = idx - 12 * EE - EE2; t = 13; u = right_u[j]; v = right_v[j]; }
    else return;
    int vb = v >> 7;
    int b = t * NBLK + vb;
    int cap  = (t < 12) ? CAP1 : CAP2;
    int base = (t < 12) ? b * CAP1 : (12 * NBLK * CAP1 + ((t - 12) * NBLK + vb) * CAP2);
    int pos = atomicAdd(&g_cnt[b], 1);
    if (pos < cap) g_edges[base + pos] = u | ((v & 127) << 18);
}

// ---------------- encoder stage 1 ----------------
__global__ __launch_bounds__(256) void enc1_kernel(
    const float* __restrict__ ctrs, const float* __restrict__ feats,
    const float* __restrict__ w_in1, const float* __restrict__ b_in1,
    const float* __restrict__ w_seg1, const float* __restrict__ b_seg1,
    float* __restrict__ h_in, float* __restrict__ h_seg)
{
    int idx = blockIdx.x * blockDim.x + threadIdx.x;
    int n = idx >> 5;
    if (n >= NN) return;
    int c = (idx & 31) * 4;

    float c0 = __ldg(&ctrs[2 * n]),  c1 = __ldg(&ctrs[2 * n + 1]);
    float f0 = __ldg(&feats[2 * n]), f1 = __ldg(&feats[2 * n + 1]);

    float4 wi0 = ld4(w_in1 + c), wi1 = ld4(w_in1 + DD + c), bi = ld4(b_in1 + c);
    float4 ws0 = ld4(w_seg1 + c), ws1 = ld4(w_seg1 + DD + c), bs = ld4(b_seg1 + c);

    float4 hi, hs;
    hi.x = fmaxf(c0 * wi0.x + c1 * wi1.x + bi.x, 0.f);
    hi.y = fmaxf(c0 * wi0.y + c1 * wi1.y + bi.y, 0.f);
    hi.z = fmaxf(c0 * wi0.z + c1 * wi1.z + bi.z, 0.f);
    hi.w = fmaxf(c0 * wi0.w + c1 * wi1.w + bi.w, 0.f);
    hs.x = fmaxf(f0 * ws0.x + f1 * ws1.x + bs.x, 0.f);
    hs.y = fmaxf(f0 * ws0.y + f1 * ws1.y + bs.y, 0.f);
    hs.z = fmaxf(f0 * ws0.z + f1 * ws1.z + bs.z, 0.f);
    hs.w = fmaxf(f0 * ws0.w + f1 * ws1.w + bs.w, 0.f);

    *(float4*)&h_in [n * DD + c] = hi;
    *(float4*)&h_seg[n * DD + c] = hs;
}

// ---------------- encoder GEMM (fp16 mma, in-place); grid.y picks the pair ----------------
__global__ __launch_bounds__(256, 2) void enc_gemm2_kernel(
    float* __restrict__ Ain, const float* __restrict__ Ba,
    float* __restrict__ Aseg, const float* __restrict__ Bb)
{
    extern __shared__ char smc[];
    uint32_t* As2 = (uint32_t*)(smc);             // [64 kpair][S2]
    uint32_t* Bs2 = (uint32_t*)(smc + 34816);

    int tid = threadIdx.x, lane = tid & 31, warp = tid >> 5;
    int gid = lane >> 2, tig = lane & 3;
    int wm = warp >> 1, wn = warp & 1;            // 4x2 grid, warp tile 32x64
    long rowBase = (long)blockIdx.x * 128;

    float* A = blockIdx.y ? Aseg : Ain;
    const float* B = blockIdx.y ? Bb : Ba;

    {
        int r = tid >> 1;
        int h = (tid & 1) * 64;
        const float* ap = A + (rowBase + r) * 128 + h;
        int hb = h >> 1;
#pragma unroll
        for (int j = 0; j < 16; j++) {
            float4 a = ld4(ap + j * 4);
            As2[(hb + j * 2 + 0) * S2 + r] = h2(a.x, a.y);
            As2[(hb + j * 2 + 1) * S2 + r] = h2(a.z, a.w);
        }
    }
#pragma unroll
    for (int j = 0; j < 8; j++) {
        int idx = tid + j * 256;
        int kp = idx >> 5, cg = (idx & 31) * 4;
        float4 lo = ld4(B + (2 * kp) * 128 + cg);
        float4 hi = ld4(B + (2 * kp + 1) * 128 + cg);
        uint4 v;
        v.x = h2(lo.x, hi.x);
        v.y = h2(lo.y, hi.y);
        v.z = h2(lo.z, hi.z);
        v.w = h2(lo.w, hi.w);
        *(uint4*)(Bs2 + kp * S2 + cg) = v;
    }
    __syncthreads();

    float acc[2][8][4];
#pragma unroll
    for (int tm = 0; tm < 2; tm++)
#pragma unroll
        for (int nt = 0; nt < 8; nt++)
#pragma unroll
            for (int j = 0; j < 4; j++) acc[tm][nt][j] = 0.f;

#pragma unroll
    for (int ks = 0; ks < 8; ks++) {
        int kk = ks * 8;
        uint32_t af[2][4];
#pragma unroll
        for (int tm = 0; tm < 2; tm++) {
            int rr = wm * 32 + tm * 16 + gid;
            const uint32_t* a0p = As2 + (kk + tig) * S2 + rr;
            const uint32_t* a1p = As2 + (kk + tig + 4) * S2 + rr;
            af[tm][0] = a0p[0];
            af[tm][1] = a0p[8];
            af[tm][2] = a1p[0];
            af[tm][3] = a1p[8];
        }
#pragma unroll
        for (int nt = 0; nt < 8; nt++) {
            int cc = wn * 64 + nt * 8 + gid;
            uint32_t b0 = Bs2[(kk + tig) * S2 + cc];
            uint32_t b1 = Bs2[(kk + tig + 4) * S2 + cc];
#pragma unroll
            for (int tm = 0; tm < 2; tm++)
                MMA_F16(acc[tm][nt], af[tm][0], af[tm][1], af[tm][2], af[tm][3], b0, b1);
        }
    }
    __syncthreads();

#pragma unroll
    for (int tm = 0; tm < 2; tm++) {
        long r0 = rowBase + wm * 32 + tm * 16 + gid;
#pragma unroll
        for (int nt = 0; nt < 8; nt++) {
            int cc = wn * 64 + nt * 8 + tig * 2;
            *(float2*)(A + r0 * 128 + cc)       = make_float2(acc[tm][nt][0], acc[tm][nt][1]);
            *(float2*)(A + (r0 + 8) * 128 + cc) = make_float2(acc[tm][nt][2], acc[tm][nt][3]);
        }
    }
}

// ---------------- GN helpers ----------------
__device__ __forceinline__ void gn_stats(float4 x, float& mean, float& kinv) {
    float s  = x.x + x.y + x.z + x.w;
    float sq = x.x * x.x + x.y * x.y + x.z * x.z + x.w * x.w;
    s  = wsum(s)  * (1.f / 128.f);
    sq = wsum(sq) * (1.f / 128.f);
    mean = s;
    float var = sq - s * s;
    kinv = rsqrtf(var + 1e-5f);
}

// enc2: feat = relu(gn(A) + gn(B)); zero A rows (tmp) for iter 0
__global__ __launch_bounds__(256) void enc2_kernel(
    float* __restrict__ A, const float* __restrict__ gA, const float* __restrict__ bA,
    const float* __restrict__ Bv, const float* __restrict__ gB, const float* __restrict__ bB,
    float* __restrict__ feat)
{
    int row = blockIdx.x * 8 + (threadIdx.x >> 5);
    if (row >= NN) return;
    int lane = threadIdx.x & 31;
    int c = lane * 4;
    float4 a = ld4(&A[(long)row * 128 + c]);
    float4 b = ld4(&Bv[(long)row * 128 + c]);
    float ma, ka, mb, kb;
    gn_stats(a, ma, ka);
    gn_stats(b, mb, kb);
    float4 ga = ld4(gA + c), ba = ld4(bA + c);
    float4 gb = ld4(gB + c), bb = ld4(bB + c);
    float4 o;
    o.x = fmaxf((a.x - ma) * ka * ga.x + ba.x + (b.x - mb) * kb * gb.x + bb.x, 0.f);
    o.y = fmaxf((a.y - ma) * ka * ga.y + ba.y + (b.y - mb) * kb * gb.y + bb.y, 0.f);
    o.z = fmaxf((a.z - ma) * ka * ga.z + ba.z + (b.z - mb) * kb * gb.z + bb.z, 0.f);
    o.w = fmaxf((a.w - ma) * ka * ga.w + ba.w + (b.w - mb) * kb * gb.w + bb.w, 0.f);
    *(float4*)&feat[(long)row * 128 + c] = o;
    *(float4*)&A   [(long)row * 128 + c] = make_float4(0.f, 0.f, 0.f, 0.f);
}

// ---------------- fused message-passing kernel (fp16 mma + ldmatrix, 1-sync pipeline) ----------------
__global__ __launch_bounds__(512) void fuse_kernel(
    const float* __restrict__ featIn, float* __restrict__ temp,
    const uint32_t* __restrict__ Wimg)
{
    extern __shared__ char smc[];
    uint32_t* CH  = (uint32_t*)(smc + F_C);   // 2 fp16 C buffers [128][RSW words]
    int*      EIX = (int*)(smc + F_E);
    int*      SCNT= (int*)(smc + F_CNT);

    uint32_t sb = smem_u32(smc);
    uint32_t eixA = sb + F_E;

    int tid = threadIdx.x, lane = tid & 31, warp = tid >> 5;
    int gid = lane >> 2, tig = lane & 3;
    int wm = warp >> 2, wn = warp & 3;            // 4x4 warp grid, tile 32x32
    int bid = blockIdx.x;
    long rowBase = (long)bid * 128;

    // --- async group 0: edge indices + B(0) ---
    for (int ch = tid; ch < 800; ch += 512) {
        int w = ch * 4;
        int srcw;
        if (w < 3072) {
            int t = w >> 8, off = w & 255;
            srcw = (t * NBLK + bid) * CAP1 + off;
        } else {
            int j = w - 3072;
            int t = j >> 6, off = j & 63;
            srcw = 12 * NBLK * CAP1 + (t * NBLK + bid) * CAP2 + off;
        }
        cpa16(eixA + w * 4, g_edges + srcw);
    }
    for (int ch = tid; ch < IMGB / 16; ch += 512)
        cpa16(sb + F_B + ch * 16, (const char*)Wimg + ch * 16);
    cp_commit();

    // --- bucket counts -> smem ---
    if (tid < 14) {
        int c = g_cnt[tid * NBLK + bid];
        int cap = (tid < 12) ? CAP1 : CAP2;
        SCNT[tid] = (c > cap) ? cap : c;
    }

    // --- A tile: row-major fp16 [row][k], stride RSW words ---
    {
        int r = tid >> 2, q = tid & 3;
        const float* ap = featIn + (rowBase + r) * 128 + q * 32;
        char* dst = smc + F_A + r * RSB + q * 64;
#pragma unroll
        for (int j = 0; j < 8; j++) {
            float4 a = ld4(ap + j * 4);
            uint2 v;
            v.x = h2(a.x, a.y);
            v.y = h2(a.z, a.w);
            *(uint2*)(dst + j * 8) = v;
        }
    }

    // per-warp ldmatrix base addresses
    uint32_t aBase = sb + F_A
        + (uint32_t)(wm * 32 + (lane & 7) + ((lane & 8) ? 8 : 0)) * RSB
        + ((lane & 16) ? 16 : 0);
    uint32_t bBase = sb + F_B
        + (uint32_t)(wn * 32 + (lane & 7) + ((lane & 16) ? 8 : 0)) * RSB
        + ((lane & 8) ? 16 : 0);

    for (int t = 0; t < 15; t++) {
        cp_wait<0>();
        __syncthreads();   // B(t) visible; C(t-1) staged; scatter(t-2) reads of CH[t&1] done

        // issue B(t+1) into other buffer
        if (t < 14) {
            const char* src = (const char*)(Wimg + (size_t)(t + 1) * IMGW);
            uint32_t dst = sb + F_B + ((t + 1) & 1) * IMGB;
            for (int ch = tid; ch < IMGB / 16; ch += 512)
                cpa16(dst + ch * 16, src + ch * 16);
            cp_commit();
        }

        // scatter(t-1): reds overlap with GEMM(t) below
        if (t > 0) {
            int s = t - 1;
            int len = SCNT[s];
            int ebase = (s < 12) ? s * CAP1 : 3072 + (s - 12) * CAP2;
            const uint32_t* Crow = CH + ((s & 1) ? CHW : 0);
            for (int e = warp; e < len; e += 16) {
                int pk = EIX[ebase + e];
                int u  = pk & 0x3FFFF;
                int vl = pk >> 18;
                uint2 w = *(const uint2*)(Crow + vl * RSW + lane * 2);
                float2 f0 = __half22float2(*(__half2*)&w.x);
                float2 f1 = __half22float2(*(__half2*)&w.y);
                redv4(temp + (long)u * 128 + lane * 4, make_float4(f0.x, f0.y, f1.x, f1.y));
            }
        }

        // GEMM(t)
        uint32_t bOff = (uint32_t)(t & 1) * IMGB;
        float acc[2][4][4];
#pragma unroll
        for (int tm = 0; tm < 2; tm++)
#pragma unroll
            for (int nt = 0; nt < 4; nt++)
#pragma unroll
                for (int j = 0; j < 4; j++) acc[tm][nt][j] = 0.f;

#pragma unroll
        for (int ks = 0; ks < 8; ks++) {
            uint32_t af0[4], af1[4], bf0[4], bf1[4];
            LDSM_X4(af0[0], af0[1], af0[2], af0[3], aBase + ks * 32);
            LDSM_X4(af1[0], af1[1], af1[2], af1[3], aBase + 16 * RSB + ks * 32);
            LDSM_X4(bf0[0], bf0[1], bf0[2], bf0[3], bBase + bOff + ks * 32);
            LDSM_X4(bf1[0], bf1[1], bf1[2], bf1[3], bBase + bOff + 16 * RSB + ks * 32);

            MMA_F16(acc[0][0], af0[0], af0[1], af0[2], af0[3], bf0[0], bf0[1]);
            MMA_F16(acc[1][0], af1[0], af1[1], af1[2], af1[3], bf0[0], bf0[1]);
            MMA_F16(acc[0][1], af0[0], af0[1], af0[2], af0[3], bf0[2], bf0[3]);
            MMA_F16(acc[1][1], af1[0], af1[1], af1[2], af1[3], bf0[2], bf0[3]);
            MMA_F16(acc[0][2], af0[0], af0[1], af0[2], af0[3], bf1[0], bf1[1]);
            MMA_F16(acc[1][2], af1[0], af1[1], af1[2], af1[3], bf1[0], bf1[1]);
            MMA_F16(acc[0][3], af0[0], af0[1], af0[2], af0[3], bf1[2], bf1[3]);
            MMA_F16(acc[1][3], af1[0], af1[1], af1[2], af1[3], bf1[2], bf1[3]);
        }

        // stage C(t) as fp16 into CH[t&1] (warp-owned rows; safe pre-sync)
        {
            uint32_t* Cw = CH + ((t & 1) ? CHW : 0);
#pragma unroll
            for (int tm = 0; tm < 2; tm++) {
                int r0 = wm * 32 + tm * 16 + gid;
#pragma unroll
                for (int nt = 0; nt < 4; nt++) {
                    int widx = wn * 16 + nt * 4 + tig;
                    Cw[r0 * RSW + widx]       = h2(acc[tm][nt][0], acc[tm][nt][1]);
                    Cw[(r0 + 8) * RSW + widx] = h2(acc[tm][nt][2], acc[tm][nt][3]);
                }
            }
        }
    }

    // epilogue: scatter(14) = ctr row-add from CH[0]
    __syncthreads();
    for (int r = warp; r < 128; r += 16) {
        uint2 w = *(const uint2*)(CH + r * RSW + lane * 2);
        float2 f0 = __half22float2(*(__half2*)&w.x);
        float2 f1 = __half22float2(*(__half2*)&w.y);
        redv4(temp + (rowBase + r) * 128 + lane * 4, make_float4(f0.x, f0.y, f1.x, f1.y));
    }
}

// ---------------- post (ldmatrix + cp.async B image) ----------------
__global__ __launch_bounds__(256, 2) void post_kernel(
    float* __restrict__ tmp, float* __restrict__ feat,
    const uint32_t* __restrict__ Bimg,
    const float* __restrict__ ng, const float* __restrict__ nb,
    const float* __restrict__ g2, const float* __restrict__ b2,
    float* __restrict__ dout, int zero_tmp, int zero_cnt)
{
    extern __shared__ char smc[];
    float* Cs = (float*)(smc);                // union over A+B after GEMM

    uint32_t sb = smem_u32(smc);
    int tid = threadIdx.x, lane = tid & 31, warp = tid >> 5;
    int gid = lane >> 2, tig = lane & 3;
    int wm = warp >> 1, wn = warp & 1;        // 4x2 grid, warp tile 32x64
    long rowBase = (long)blockIdx.x * 128;

    // async: B image -> smem (overlaps GN prologue)
    for (int ch = tid; ch < IMGB / 16; ch += 256)
        cpa16(sb + 34816 + ch * 16, (const char*)Bimg + ch * 16);
    cp_commit();

    // restore bucket counters for next replay (once, at last layer)
    if (zero_cnt && tid < 14) g_cnt[blockIdx.x * 14 + tid] = 0;

    // prologue: GN1 + relu -> fp16 row-major [row][k] into A region; optional zero tmp
    {
        int r = tid >> 1;
        int h = (tid & 1) * 64;
        float* xp = tmp + (rowBase + r) * 128 + h;
        float s = 0.f, sq = 0.f;
        float4 av[16];
#pragma unroll
        for (int j = 0; j < 16; j++) {
            av[j] = ld4(xp + j * 4);
            s  += av[j].x + av[j].y + av[j].z + av[j].w;
            sq += av[j].x * av[j].x + av[j].y * av[j].y + av[j].z * av[j].z + av[j].w * av[j].w;
        }
        s  += __shfl_xor_sync(0xffffffffu, s, 1);
        sq += __shfl_xor_sync(0xffffffffu, sq, 1);
        float mean = s * (1.f / 128.f);
        float kinv = rsqrtf(sq * (1.f / 128.f) - mean * mean + 1e-5f);
        char* dst = smc + r * RSB + (h >> 1) * 4;
#pragma unroll
        for (int j = 0; j < 16; j++) {
            int k = h + j * 4;
            float4 gg = ld4(ng + k), bb = ld4(nb + k);
            float ox = fmaxf((av[j].x - mean) * kinv * gg.x + bb.x, 0.f);
            float oy = fmaxf((av[j].y - mean) * kinv * gg.y + bb.y, 0.f);
            float oz = fmaxf((av[j].z - mean) * kinv * gg.z + bb.z, 0.f);
            float ow = fmaxf((av[j].w - mean) * kinv * gg.w + bb.w, 0.f);
            uint2 v;
            v.x = h2(ox, oy);
            v.y = h2(oz, ow);
            *(uint2*)(dst + j * 8) = v;
        }
        if (zero_tmp) {
            float4 z = make_float4(0.f, 0.f, 0.f, 0.f);
#pragma unroll
            for (int j = 0; j < 16; j++) *(float4*)(xp + j * 4) = z;
        }
    }
    cp_wait<0>();
    __syncthreads();

    // ldmatrix bases
    uint32_t aBase = sb
        + (uint32_t)(wm * 32 + (lane & 7) + ((lane & 8) ? 8 : 0)) * RSB
        + ((lane & 16) ? 16 : 0);
    uint32_t bBase = sb + 34816
        + (uint32_t)(wn * 64 + (lane & 7) + ((lane & 16) ? 8 : 0)) * RSB
        + ((lane & 8) ? 16 : 0);

    float acc[2][8][4];
#pragma unroll
    for (int tm = 0; tm < 2; tm++)
#pragma unroll
        for (int nt = 0; nt < 8; nt++)
#pragma unroll
            for (int j = 0; j < 4; j++) acc[tm][nt][j] = 0.f;

#pragma unroll
    for (int ks = 0; ks < 8; ks++) {
        uint32_t af0[4], af1[4];
        LDSM_X4(af0[0], af0[1], af0[2], af0[3], aBase + ks * 32);
        LDSM_X4(af1[0], af1[1], af1[2], af1[3], aBase + 16 * RSB + ks * 32);
#pragma unroll
        for (int g = 0; g < 4; g++) {
            uint32_t bf[4];
            LDSM_X4(bf[0], bf[1], bf[2], bf[3], bBase + (uint32_t)g * 16 * RSB + ks * 32);
            MMA_F16(acc[0][2 * g],     af0[0], af0[1], af0[2], af0[3], bf[0], bf[1]);
            MMA_F16(acc[1][2 * g],     af1[0], af1[1], af1[2], af1[3], bf[0], bf[1]);
            MMA_F16(acc[0][2 * g + 1], af0[0], af0[1], af0[2], af0[3], bf[2], bf[3]);
            MMA_F16(acc[1][2 * g + 1], af1[0], af1[1], af1[2], af1[3], bf[2], bf[3]);
        }
    }
    __syncthreads();   // done reading A/B before Cs overwrite

    // stage C (fp32) into union region
#pragma unroll
    for (int tm = 0; tm < 2; tm++) {
        int r0 = wm * 32 + tm * 16 + gid;
#pragma unroll
        for (int nt = 0; nt < 8; nt++) {
            int cc = wn * 64 + nt * 8 + tig * 2;
            *(float2*)(Cs + r0 * CSTR + cc)       = make_float2(acc[tm][nt][0], acc[tm][nt][1]);
            *(float2*)(Cs + (r0 + 8) * CSTR + cc) = make_float2(acc[tm][nt][2], acc[tm][nt][3]);
        }
    }
    __syncthreads();

    // epilogue: GN2 + residual + relu
    for (int r = warp; r < 128; r += 8) {
        int c = lane * 4;
        float4 x = *(float4*)(Cs + r * CSTR + c);
        float m, k;
        gn_stats(x, m, k);
        float4 gg = ld4(g2 + c), bb = ld4(b2 + c);
        long grow = rowBase + r;
        float4 old = ld4(feat + grow * 128 + c);
        float4 o;
        o.x = fmaxf((x.x - m) * k * gg.x + bb.x + old.x, 0.f);
        o.y = fmaxf((x.y - m) * k * gg.y + bb.y + old.y, 0.f);
        o.z = fmaxf((x.z - m) * k * gg.z + bb.z + old.z, 0.f);
        o.w = fmaxf((x.w - m) * k * gg.w + bb.w + old.w, 0.f);
        *(float4*)(feat + grow * 128 + c) = o;
        if (dout && grow < NN) *(float4*)(dout + grow * 128 + c) = o;
    }
}

// ---------------- host launcher ----------------
extern "C" void kernel_launch(void* const* d_in, const int* in_sizes, int n_in,
                              void* d_out, int out_size)
{
    const float* ctrs   = (const float*)d_in[0];
    const float* feats  = (const float*)d_in[1];
    const float* w_in1  = (const float*)d_in[2];
    const float* b_in1  = (const float*)d_in[3];
    const float* w_in2  = (const float*)d_in[4];
    const float* g_in   = (const float*)d_in[5];
    const float* be_in  = (const float*)d_in[6];
    const float* w_seg1 = (const float*)d_in[7];
    const float* b_seg1 = (const float*)d_in[8];
    const float* w_seg2 = (const float*)d_in[9];
    const float* g_seg  = (const float*)d_in[10];
    const float* be_seg = (const float*)d_in[11];
    const float* ctr_w  = (const float*)d_in[12];
    const float* pre_w  = (const float*)d_in[13];
    const float* suc_w  = (const float*)d_in[14];
    const float* left_w = (const float*)d_in[15];
    const float* right_w= (const float*)d_in[16];
    const float* norm_g = (const float*)d_in[17];
    const float* norm_b = (const float*)d_in[18];
    const float* ctr2_w = (const float*)d_in[19];
    const float* ctr2_g = (const float*)d_in[20];
    const float* ctr2_b = (const float*)d_in[21];
    const int* pre_u  = (const int*)d_in[22];
    const int* pre_v  = (const int*)d_in[23];
    const int* suc_u  = (const int*)d_in[24];
    const int* suc_v  = (const int*)d_in[25];
    const int* left_u = (const int*)d_in[26];
    const int* left_v = (const int*)d_in[27];
    const int* right_u= (const int*)d_in[28];
    const int* right_v= (const int*)d_in[29];

    float *feat, *tmp, *y;
    uint32_t *wimg;
    cudaGetSymbolAddress((void**)&feat, g_feat);
    cudaGetSymbolAddress((void**)&tmp,  g_tmp);
    cudaGetSymbolAddress((void**)&y,    g_y);
    cudaGetSymbolAddress((void**)&wimg, g_wimg);

    const int EB = (TOTAL_E + 255) / 256;

    static bool attr_set = false;
    if (!attr_set) {
        cudaFuncSetAttribute(enc_gemm2_kernel, cudaFuncAttributeMaxDynamicSharedMemorySize, SMEM_ENC);
        cudaFuncSetAttribute(post_kernel,      cudaFuncAttributeMaxDynamicSharedMemorySize, SMEM_POST);
        cudaFuncSetAttribute(fuse_kernel,      cudaFuncAttributeMaxDynamicSharedMemorySize, SMEM_FUSE4);
        attr_set = true;
    }

    // g_cnt is zero: zero-initialized at module load; re-zeroed by post(i=3) each call.
    place_kernel<<<EB, 256>>>(pre_u, pre_v, suc_u, suc_v, left_u, left_v, right_u, right_v);
    prep_kernel<<<64, 256>>>(pre_w, suc_w, left_w, right_w, ctr_w, ctr2_w);

    enc1_kernel<<<(NN * 32) / 256, 256>>>(ctrs, feats, w_in1, b_in1, w_seg1, b_seg1, tmp, y);
    enc_gemm2_kernel<<<dim3(NBLK, 2), 256, SMEM_ENC>>>(tmp, w_in2, y, w_seg2);
    enc2_kernel<<<NN / 8, 256>>>(tmp, g_in, be_in, y, g_seg, be_seg, feat);

    for (int i = 0; i < LL; i++) {
        fuse_kernel<<<NBLK, 512, SMEM_FUSE4>>>(feat, tmp, wimg + (size_t)i * NIMG * IMGW);
        post_kernel<<<NBLK, 256, SMEM_POST>>>(
            tmp, feat, wimg + ((size_t)i * NIMG + 15) * IMGW,
            norm_g + i * 128, norm_b + i * 128,
            ctr2_g + i * 128, ctr2_b + i * 128,
            (i == LL - 1) ? (float*)d_out : nullptr,
            (i < LL - 1) ? 1 : 0,
            (i == LL - 1) ? 1 : 0);
    }
}